// round 6
// baseline (speedup 1.0000x reference)
#include <cuda_runtime.h>
#include <cuda_bf16.h>
#include <float.h>
#include <math.h>

#define S 2048
#define D 1024
#define NMEM 32
#define PATCH 32
#define RTILES 64                     // tiles per source for rowstats (32 rows each)

// ---------------- scratch (static device globals; no allocation) ----------------
__device__ float g_entropy [NMEM * S];
__device__ float g_entropy2[S];
__device__ float g_part    [(NMEM + 2) * RTILES * D];
__device__ float g_colmean [(NMEM + 1) * D];
__device__ unsigned long long g_cand[NMEM * 8 * 32];
__device__ int   g_topidx  [NMEM * PATCH];
__device__ int   g_fidx    [PATCH];
__device__ float g_agg     [S * D];   // query + scattered patches (= aggregated*33)
__device__ float g_emb     [(NMEM + 1) * D];
__device__ float g_norm    [NMEM + 1];

// ---------------- cp.async helpers --------------------------------------------------
__device__ __forceinline__ void cp_async16(float* sdst, const float* gsrc)
{
    unsigned sa = (unsigned)__cvta_generic_to_shared(sdst);
    asm volatile("cp.async.cg.shared.global [%0], [%1], 16;" :: "r"(sa), "l"(gsrc) : "memory");
}
__device__ __forceinline__ void issue_row(const float* g, float* slot, int l)
{
#pragma unroll
    for (int j = 0; j < 8; j++)
        cp_async16(slot + (l + 32 * j) * 4, g + (l + 32 * j) * 4);
    asm volatile("cp.async.commit_group;" ::: "memory");
}

// ---------------- kernel A: row stats + partial colsums, 4-slot cp.async ring -------
// grid = n_count*RTILES blocks, 128 threads (4 warps). Warp w: rows tile*32 + w*8 .. +7.
// dynamic smem: ring[4 warps][4 slots][1024 floats] = 64KB (reused as cs[4][1024])
__global__ void __launch_bounds__(128)
rowstats_kernel(const float* __restrict__ src_in, int esel, int part_base)
{
    extern __shared__ float sm[];
    const float* src = src_in ? src_in : g_agg;
    const int bx = blockIdx.x;
    const int tile = bx & (RTILES - 1);
    const int n    = bx >> 6;
    const int t = threadIdx.x;
    const int w = t >> 5, l = t & 31;

    const int row0 = tile * 32 + w * 8;
    const float* rowbase = src + (size_t)n * S * D + (size_t)row0 * D;
    float* ring = sm + w * 4096;

    // prime 3 rows
    issue_row(rowbase + 0 * (size_t)D, ring + 0 * 1024, l);
    issue_row(rowbase + 1 * (size_t)D, ring + 1 * 1024, l);
    issue_row(rowbase + 2 * (size_t)D, ring + 2 * 1024, l);

    float4 colacc[8];
#pragma unroll
    for (int j = 0; j < 8; j++) colacc[j] = make_float4(0.f, 0.f, 0.f, 0.f);
    float s1[8], s2[8];

#pragma unroll
    for (int k = 0; k < 8; k++) {
        if (k <= 5)      asm volatile("cp.async.wait_group 2;" ::: "memory");
        else if (k == 6) asm volatile("cp.async.wait_group 1;" ::: "memory");
        else             asm volatile("cp.async.wait_group 0;" ::: "memory");
        // slot data is strictly thread-private (same lane wrote it) -> no barrier
        const float4* rp = reinterpret_cast<const float4*>(ring + (k & 3) * 1024);
        float a = 0.f, b = 0.f;
#pragma unroll
        for (int j = 0; j < 8; j++) {
            float4 x = rp[l + 32 * j];
            colacc[j].x += x.x; colacc[j].y += x.y; colacc[j].z += x.z; colacc[j].w += x.w;
            a += (x.x + x.y) + (x.z + x.w);
            b += (x.x * x.x + x.y * x.y) + (x.z * x.z + x.w * x.w);
        }
        s1[k] = a; s2[k] = b;
        if (k < 5) issue_row(rowbase + (size_t)(k + 3) * D, ring + ((k + 3) & 3) * 1024, l);
    }

    // batched fp32 butterfly: 80 independent shuffles
#pragma unroll
    for (int off = 16; off; off >>= 1) {
#pragma unroll
        for (int k = 0; k < 8; k++) {
            s1[k] += __shfl_xor_sync(0xffffffffu, s1[k], off);
            s2[k] += __shfl_xor_sync(0xffffffffu, s2[k], off);
        }
    }
    // lane k stores entropy for row row0+k (pure fp32: no FP64 on B300!)
#pragma unroll
    for (int k = 0; k < 8; k++) {
        if (l == k) {
            float var = (s2[k] - s1[k] * s1[k] * (1.0f / (float)D)) * (1.0f / (float)(D - 1));
            float e = var > 0.f ? sqrtf(var) : 0.f;
            if (esel == 0) g_entropy[(size_t)n * S + row0 + k] = e;
            else           g_entropy2[row0 + k] = e;
        }
    }

    // deterministic column-sum combine (reuse smem as cs[4][1024])
    __syncthreads();
    float* cs = sm;
#pragma unroll
    for (int j = 0; j < 8; j++)
        reinterpret_cast<float4*>(&cs[w * 1024 + 4 * (l + 32 * j)])[0] = colacc[j];
    __syncthreads();
#pragma unroll
    for (int g = 0; g < 8; g++) {
        const int d = t + 128 * g;
        float ssum = ((cs[0 * 1024 + d] + cs[1 * 1024 + d]) +
                      (cs[2 * 1024 + d] + cs[3 * 1024 + d]));
        g_part[(size_t)(part_base + bx) * D + d] = ssum;
    }
}

// ---------------- kernel B: reduce partial colsums -> colmean ----------------------
__global__ void colmean_kernel(int n0)
{
    const int n = n0 + blockIdx.x, t = threadIdx.x;
#pragma unroll
    for (int g = 0; g < 4; g++) {
        const int d = t + 256 * g;
        float s = 0.f;
#pragma unroll 8
        for (int p = 0; p < RTILES; p++) s += g_part[(size_t)(n * RTILES + p) * D + d];
        g_colmean[n * D + d] = s * (1.0f / (float)S);
    }
}

// ---------------- topk phase 1: each 1-warp block -> top-32 of its 256 elems --------
// key = (float_bits << 32) | ~row  (u64 max == value desc, then lowest row)
__global__ void topk1_kernel(int esel)
{
    const int b = blockIdx.x, l = threadIdx.x;
    const float* e = (esel == 0 ? g_entropy : g_entropy2) + (size_t)b * 256;

    unsigned long long key[8];
#pragma unroll
    for (int j = 0; j < 8; j++) {
        const int loc = l + 32 * j;
        const int row = ((b & 7) * 256 + loc);
        const unsigned v = __float_as_uint(e[loc]);   // entropy >= 0
        key[j] = ((unsigned long long)v << 32) | (unsigned)(~row);
    }
    for (int it = 0; it < 32; it++) {
        unsigned long long m = key[0];
#pragma unroll
        for (int j = 1; j < 8; j++) m = (key[j] > m) ? key[j] : m;
#pragma unroll
        for (int off = 16; off; off >>= 1) {
            unsigned long long o = __shfl_xor_sync(0xffffffffu, m, off);
            m = (o > m) ? o : m;
        }
        if (l == 0) g_cand[b * 32 + it] = m;
#pragma unroll
        for (int j = 0; j < 8; j++) if (key[j] == m) key[j] = 0ull;
    }
}

// ---------------- topk phase 2: exact rank among 256 candidates ---------------------
__global__ void topk2_kernel(int osel)
{
    __shared__ unsigned long long c[256];
    const int n = blockIdx.x, t = threadIdx.x;
    const unsigned long long k = g_cand[n * 256 + t];
    c[t] = k;
    __syncthreads();
    int r = 0;
#pragma unroll 8
    for (int i = 0; i < 256; i++) r += (c[i] > k) ? 1 : 0;
    if (r < PATCH) {
        const int row = (int)(~(unsigned)(k & 0xffffffffu));
        if (osel == 0) g_topidx[n * PATCH + r] = row;
        else           g_fidx[r] = row;
    }
}

// ---------------- kernel D: agg = query copy, out[0..S*D) = 0 -----------------------
__global__ void init_agg_kernel(const float* __restrict__ q, float* __restrict__ out)
{
    const int i = blockIdx.x * blockDim.x + threadIdx.x;
    float4 v = reinterpret_cast<const float4*>(q)[i];
    reinterpret_cast<float4*>(g_agg)[i] = v;
    reinterpret_cast<float4*>(out)[i] = make_float4(0.f, 0.f, 0.f, 0.f);
}

__device__ __forceinline__ float trunc_clip(float x)
{
    return truncf(fminf(fmaxf(x, -128.f), 127.f));
}

// ---------------- kernel E: scatter truncated patches into agg ----------------------
__global__ void scatter_kernel(const float* __restrict__ mem)
{
    const int b = blockIdx.x;
    const int n = b >> 5, j = b & 31;
    const int row = g_topidx[n * PATCH + j];
    const int t = threadIdx.x;
    float4 x = reinterpret_cast<const float4*>(mem + ((size_t)n * S + row) * D)[t];
    float* dst = g_agg + (size_t)row * D + 4 * t;
    atomicAdd(dst + 0, trunc_clip(x.x));
    atomicAdd(dst + 1, trunc_clip(x.y));
    atomicAdd(dst + 2, trunc_clip(x.z));
    atomicAdd(dst + 3, trunc_clip(x.w));
}

// ---------------- kernel H: write recon rows -----------------------------------------
__global__ void recon_kernel(float* __restrict__ out)
{
    const int row = g_fidx[blockIdx.x];
    const int t = threadIdx.x;
    float4 x = reinterpret_cast<float4*>(g_agg + (size_t)row * D)[t];
    const float inv = 1.0f / 33.0f;
    float4 r;
    r.x = trunc_clip(x.x * inv);
    r.y = trunc_clip(x.y * inv);
    r.z = trunc_clip(x.z * inv);
    r.w = trunc_clip(x.w * inv);
    reinterpret_cast<float4*>(out + (size_t)row * D)[t] = r;
}

// ---------------- kernel M: meta MLP (33 blocks x 128 threads, all fp32) -------------
__global__ void mlp_kernel(const float* __restrict__ surprise,
                           const float* __restrict__ W1, const float* __restrict__ b1,
                           const float* __restrict__ W2, const float* __restrict__ b2)
{
    const int n = blockIdx.x;       // 0..31 memories, 32 = query
    const int t = threadIdx.x;      // 128
    __shared__ float feat[1028];
    __shared__ float hsm[128];
    __shared__ float red[128];

#pragma unroll
    for (int g = 0; g < 8; g++) feat[t + 128 * g] = g_colmean[n * D + t + 128 * g];
    if (t == 0) {
        feat[1024] = (n < NMEM) ? surprise[n] : 0.f;
        feat[1025] = 0.f; feat[1026] = 0.f;
    }
    __syncthreads();

    float a0 = b1[t], a1 = 0.f, a2 = 0.f, a3 = 0.f;
    for (int i = 0; i < 1024; i += 4) {
        a0 = fmaf(feat[i + 0], W1[(i + 0) * 128 + t], a0);
        a1 = fmaf(feat[i + 1], W1[(i + 1) * 128 + t], a1);
        a2 = fmaf(feat[i + 2], W1[(i + 2) * 128 + t], a2);
        a3 = fmaf(feat[i + 3], W1[(i + 3) * 128 + t], a3);
    }
    for (int i = 1024; i < 1027; i++) a0 = fmaf(feat[i], W1[i * 128 + t], a0);
    float acc = (a0 + a1) + (a2 + a3);
    hsm[t] = acc > 0.f ? acc : 0.f;
    __syncthreads();

    float nrm = 0.f;
#pragma unroll
    for (int g = 0; g < 8; g++) {
        const int d = t + 128 * g;
        float e0 = b2[d], e1 = 0.f, e2 = 0.f, e3 = 0.f;
#pragma unroll
        for (int k = 0; k < 128; k += 4) {
            e0 = fmaf(hsm[k + 0], W2[(k + 0) * D + d], e0);
            e1 = fmaf(hsm[k + 1], W2[(k + 1) * D + d], e1);
            e2 = fmaf(hsm[k + 2], W2[(k + 2) * D + d], e2);
            e3 = fmaf(hsm[k + 3], W2[(k + 3) * D + d], e3);
        }
        float e = (e0 + e1) + (e2 + e3);
        g_emb[n * D + d] = e;
        nrm = fmaf(e, e, nrm);
    }
    red[t] = nrm;
    __syncthreads();
#pragma unroll
    for (int off = 64; off; off >>= 1) { if (t < off) red[t] += red[t + off]; __syncthreads(); }
    if (t == 0) g_norm[n] = sqrtf(red[0]);
}

// ---------------- kernel S: sims + rank-ordered top_idx (fp32, 1 block) -------------
__global__ void __launch_bounds__(1024) sims_kernel(const float* __restrict__ pm,
                                                    float* __restrict__ out)
{
    const int t = threadIdx.x, w = t >> 5, l = t & 31;   // w = memory index
    const float4* en = reinterpret_cast<const float4*>(g_emb + (size_t)w * D) + l * 8;
    const float4* eq = reinterpret_cast<const float4*>(g_emb + (size_t)NMEM * D) + l * 8;
    float a0 = 0.f, a1 = 0.f, a2 = 0.f, a3 = 0.f;
#pragma unroll
    for (int j = 0; j < 8; j++) {
        float4 x = en[j], y = eq[j];
        a0 = fmaf(x.x, y.x, a0);
        a1 = fmaf(x.y, y.y, a1);
        a2 = fmaf(x.z, y.z, a2);
        a3 = fmaf(x.w, y.w, a3);
    }
    float p = (a0 + a1) + (a2 + a3);
#pragma unroll
    for (int off = 16; off; off >>= 1) p += __shfl_xor_sync(0xffffffffu, p, off);

    __shared__ float ssim[NMEM];
    if (l == 0) {
        float sim = p / (fmaxf(g_norm[w], 1e-8f) * fmaxf(g_norm[NMEM], 1e-8f)) * pm[w];
        out[(size_t)S * D + w] = sim;
        ssim[w] = sim;
    }
    __syncthreads();
    if (w == 0) {
        const float v = ssim[l];
        int r = 0;
#pragma unroll
        for (int i = 0; i < NMEM; i++) {
            const float vi = ssim[i];
            r += ((vi > v) || (vi == v && i < l)) ? 1 : 0;
        }
        out[(size_t)S * D + NMEM + r] = (float)l;
    }
}

// ---------------- launch ------------------------------------------------------------
extern "C" void kernel_launch(void* const* d_in, const int* in_sizes, int n_in,
                              void* d_out, int out_size)
{
    const float* query    = (const float*)d_in[0];
    const float* memories = (const float*)d_in[1];
    const float* surprise = (const float*)d_in[2];
    const float* pm       = (const float*)d_in[3];
    const float* W1       = (const float*)d_in[4];
    const float* b1       = (const float*)d_in[5];
    const float* W2       = (const float*)d_in[6];
    const float* b2       = (const float*)d_in[7];
    float* out = (float*)d_out;

    const int RS_SMEM = 64 * 1024;
    static int attr_done = 0;
    if (!attr_done) {
        cudaFuncSetAttribute(rowstats_kernel,
                             cudaFuncAttributeMaxDynamicSharedMemorySize, RS_SMEM);
        attr_done = 1;
    }

    // 1) agg = query, zero recon region of out
    init_agg_kernel<<<(S * D / 4) / 256, 256>>>(query, out);
    // 2) query column sums (entropy -> g_entropy2 scratch, overwritten later)
    rowstats_kernel<<<RTILES, 128, RS_SMEM>>>(query, 1, NMEM * RTILES);
    // 3) query colmean (slot 32)
    colmean_kernel<<<1, 256>>>(NMEM);
    // 4) per-memory row entropy + partial colsums (268MB pass)  <- profiled slot
    rowstats_kernel<<<NMEM * RTILES, 128, RS_SMEM>>>(memories, 0, 0);
    // 5-6) per-memory top-32 entropy rows
    topk1_kernel<<<NMEM * 8, 32>>>(0);
    topk2_kernel<<<NMEM, 256>>>(0);
    // 7) scatter truncated patches (exact integer fp adds)
    scatter_kernel<<<NMEM * PATCH, 256>>>(memories);
    // 8) row entropy of aggregated
    rowstats_kernel<<<RTILES, 128, RS_SMEM>>>(nullptr, 1, (NMEM + 1) * RTILES);
    // 9-10) final top-32 rows
    topk1_kernel<<<8, 32>>>(1);
    topk2_kernel<<<1, 256>>>(1);
    // 11) recon rows (trunc(clip(agg/33)))
    recon_kernel<<<PATCH, 256>>>(out);
    // 12) memory colmeans
    colmean_kernel<<<NMEM, 256>>>(0);
    // 13) meta-learner embeddings + norms
    mlp_kernel<<<NMEM + 1, 128>>>(surprise, W1, b1, W2, b2);
    // 14) sims + top_idx
    sims_kernel<<<1, 1024>>>(pm, out);
}

// round 7
// speedup vs baseline: 1.3113x; 1.3113x over previous
#include <cuda_runtime.h>
#include <cuda_bf16.h>
#include <float.h>
#include <math.h>

#define S 2048
#define D 1024
#define NMEM 32
#define PATCH 32
#define RTILES 64                     // tiles per source (32 rows each)

// ---------------- scratch (static device globals; no allocation) ----------------
__device__ float g_entropy [NMEM * S];
__device__ float g_entropy2[S];
__device__ float g_part    [(NMEM + 2) * RTILES * D];
__device__ float g_colmean [(NMEM + 1) * D];
__device__ unsigned long long g_cand[NMEM * 8 * 32];
__device__ int   g_topidx  [NMEM * PATCH];
__device__ int   g_fidx    [PATCH];
__device__ float g_agg     [S * D];   // query + scattered patches (= aggregated*33)
__device__ float g_emb     [(NMEM + 1) * D];
__device__ float g_norm    [NMEM + 1];

// ---------------- cp.async helpers --------------------------------------------------
__device__ __forceinline__ void cp_async16(float* sdst, const float* gsrc)
{
    unsigned sa = (unsigned)__cvta_generic_to_shared(sdst);
    asm volatile("cp.async.cg.shared.global [%0], [%1], 16;" :: "r"(sa), "l"(gsrc) : "memory");
}
// one 2KB half-row chunk: lane l copies 4 x 16B, commit as one group
__device__ __forceinline__ void issue_chunk(const float* g, float* slot, int l)
{
#pragma unroll
    for (int j = 0; j < 4; j++)
        cp_async16(slot + (l + 32 * j) * 4, g + (l + 32 * j) * 4);
    asm volatile("cp.async.commit_group;" ::: "memory");
}

// ---------------- kernel A: row stats + partial colsums ------------------------------
// STATIC 32KB smem only (no carveout escalation). grid = n_count*RTILES blocks,
// 128 threads (4 warps). Warp w handles rows tile*32 + w*8 .. +7, as 16 half-row
// chunks through a 4-slot/2KB ring (3 chunks in flight).
__global__ void __launch_bounds__(128)
rowstats_kernel(const float* __restrict__ src_in, int esel, int part_base)
{
    __shared__ float sm[8192];        // 32KB: ring[4 warps][4 slots][512]; reused as cs
    const float* src = src_in ? src_in : g_agg;
    const int bx = blockIdx.x;
    const int tile = bx & (RTILES - 1);
    const int n    = bx >> 6;
    const int t = threadIdx.x;
    const int w = t >> 5, l = t & 31;

    const int row0 = tile * 32 + w * 8;
    const float* rowbase = src + (size_t)n * S * D + (size_t)row0 * D;
    float* ring = sm + w * 2048;

    // prime 3 chunks (chunk k: row k>>1, half k&1)
    issue_chunk(rowbase + 0,                ring + 0 * 512, l);
    issue_chunk(rowbase + 512,              ring + 1 * 512, l);
    issue_chunk(rowbase + (size_t)D,        ring + 2 * 512, l);

    float4 colacc[8];
#pragma unroll
    for (int j = 0; j < 8; j++) colacc[j] = make_float4(0.f, 0.f, 0.f, 0.f);
    float s1[8], s2[8];
#pragma unroll
    for (int k = 0; k < 8; k++) { s1[k] = 0.f; s2[k] = 0.f; }

#pragma unroll
    for (int k = 0; k < 16; k++) {
        if (k <= 13)     asm volatile("cp.async.wait_group 2;" ::: "memory");
        else if (k == 14) asm volatile("cp.async.wait_group 1;" ::: "memory");
        else              asm volatile("cp.async.wait_group 0;" ::: "memory");
        // slot data is strictly thread-private (same lane wrote it) -> no barrier
        const float4* rp = reinterpret_cast<const float4*>(ring + (k & 3) * 512);
        const int half = k & 1;
        float a = 0.f, b = 0.f;
#pragma unroll
        for (int j = 0; j < 4; j++) {
            float4 x = rp[l + 32 * j];
            const int c = half * 4 + j;
            colacc[c].x += x.x; colacc[c].y += x.y; colacc[c].z += x.z; colacc[c].w += x.w;
            a += (x.x + x.y) + (x.z + x.w);
            b += (x.x * x.x + x.y * x.y) + (x.z * x.z + x.w * x.w);
        }
        s1[k >> 1] += a; s2[k >> 1] += b;
        if (k < 13) {
            const int kn = k + 3;
            issue_chunk(rowbase + (size_t)(kn >> 1) * D + (kn & 1) * 512,
                        ring + (kn & 3) * 512, l);
        }
    }

    // batched fp32 butterfly: 80 independent shuffles
#pragma unroll
    for (int off = 16; off; off >>= 1) {
#pragma unroll
        for (int k = 0; k < 8; k++) {
            s1[k] += __shfl_xor_sync(0xffffffffu, s1[k], off);
            s2[k] += __shfl_xor_sync(0xffffffffu, s2[k], off);
        }
    }
#pragma unroll
    for (int k = 0; k < 8; k++) {
        if (l == k) {
            float var = (s2[k] - s1[k] * s1[k] * (1.0f / (float)D)) * (1.0f / (float)(D - 1));
            float e = var > 0.f ? sqrtf(var) : 0.f;
            if (esel == 0) g_entropy[(size_t)n * S + row0 + k] = e;
            else           g_entropy2[row0 + k] = e;
        }
    }

    // deterministic column-sum combine (reuse smem as cs[4][1024])
    __syncthreads();
    float* cs = sm;
#pragma unroll
    for (int h = 0; h < 2; h++)
#pragma unroll
        for (int j = 0; j < 4; j++)
            reinterpret_cast<float4*>(&cs[w * 1024 + h * 512 + 4 * (l + 32 * j)])[0]
                = colacc[h * 4 + j];
    __syncthreads();
#pragma unroll
    for (int g = 0; g < 8; g++) {
        const int d = t + 128 * g;
        float ssum = ((cs[0 * 1024 + d] + cs[1 * 1024 + d]) +
                      (cs[2 * 1024 + d] + cs[3 * 1024 + d]));
        g_part[(size_t)(part_base + bx) * D + d] = ssum;
    }
}

// ---------------- kernel B: reduce partial colsums -> colmean ----------------------
__global__ void colmean_kernel(int n0)
{
    const int n = n0 + blockIdx.x, t = threadIdx.x;
#pragma unroll
    for (int g = 0; g < 4; g++) {
        const int d = t + 256 * g;
        float s = 0.f;
#pragma unroll 8
        for (int p = 0; p < RTILES; p++) s += g_part[(size_t)(n * RTILES + p) * D + d];
        g_colmean[n * D + d] = s * (1.0f / (float)S);
    }
}

// ---------------- topk phase 1: each 1-warp block -> top-32 of its 256 elems --------
// key = (float_bits << 32) | ~row  (u64 max == value desc, then lowest row)
__global__ void topk1_kernel(int esel)
{
    const int b = blockIdx.x, l = threadIdx.x;
    const float* e = (esel == 0 ? g_entropy : g_entropy2) + (size_t)b * 256;

    unsigned long long key[8];
#pragma unroll
    for (int j = 0; j < 8; j++) {
        const int loc = l + 32 * j;
        const int row = ((b & 7) * 256 + loc);
        const unsigned v = __float_as_uint(e[loc]);   // entropy >= 0
        key[j] = ((unsigned long long)v << 32) | (unsigned)(~row);
    }
    for (int it = 0; it < 32; it++) {
        unsigned long long m = key[0];
#pragma unroll
        for (int j = 1; j < 8; j++) m = (key[j] > m) ? key[j] : m;
#pragma unroll
        for (int off = 16; off; off >>= 1) {
            unsigned long long o = __shfl_xor_sync(0xffffffffu, m, off);
            m = (o > m) ? o : m;
        }
        if (l == 0) g_cand[b * 32 + it] = m;
#pragma unroll
        for (int j = 0; j < 8; j++) if (key[j] == m) key[j] = 0ull;
    }
}

// ---------------- topk phase 2: exact rank among 256 candidates ---------------------
__global__ void topk2_kernel(int osel)
{
    __shared__ unsigned long long c[256];
    const int n = blockIdx.x, t = threadIdx.x;
    const unsigned long long k = g_cand[n * 256 + t];
    c[t] = k;
    __syncthreads();
    int r = 0;
#pragma unroll 8
    for (int i = 0; i < 256; i++) r += (c[i] > k) ? 1 : 0;
    if (r < PATCH) {
        const int row = (int)(~(unsigned)(k & 0xffffffffu));
        if (osel == 0) g_topidx[n * PATCH + r] = row;
        else           g_fidx[r] = row;
    }
}

// ---------------- kernel D: agg = query copy, out[0..S*D) = 0 -----------------------
__global__ void init_agg_kernel(const float* __restrict__ q, float* __restrict__ out)
{
    const int i = blockIdx.x * blockDim.x + threadIdx.x;
    float4 v = reinterpret_cast<const float4*>(q)[i];
    reinterpret_cast<float4*>(g_agg)[i] = v;
    reinterpret_cast<float4*>(out)[i] = make_float4(0.f, 0.f, 0.f, 0.f);
}

__device__ __forceinline__ float trunc_clip(float x)
{
    return truncf(fminf(fmaxf(x, -128.f), 127.f));
}

// ---------------- kernel E: scatter truncated patches into agg ----------------------
__global__ void scatter_kernel(const float* __restrict__ mem)
{
    const int b = blockIdx.x;
    const int n = b >> 5, j = b & 31;
    const int row = g_topidx[n * PATCH + j];
    const int t = threadIdx.x;
    float4 x = reinterpret_cast<const float4*>(mem + ((size_t)n * S + row) * D)[t];
    float* dst = g_agg + (size_t)row * D + 4 * t;
    atomicAdd(dst + 0, trunc_clip(x.x));
    atomicAdd(dst + 1, trunc_clip(x.y));
    atomicAdd(dst + 2, trunc_clip(x.z));
    atomicAdd(dst + 3, trunc_clip(x.w));
}

// ---------------- kernel H: write recon rows -----------------------------------------
__global__ void recon_kernel(float* __restrict__ out)
{
    const int row = g_fidx[blockIdx.x];
    const int t = threadIdx.x;
    float4 x = reinterpret_cast<float4*>(g_agg + (size_t)row * D)[t];
    const float inv = 1.0f / 33.0f;
    float4 r;
    r.x = trunc_clip(x.x * inv);
    r.y = trunc_clip(x.y * inv);
    r.z = trunc_clip(x.z * inv);
    r.w = trunc_clip(x.w * inv);
    reinterpret_cast<float4*>(out + (size_t)row * D)[t] = r;
}

// ---------------- kernel M: meta MLP (33 blocks x 128 threads, fp32) -----------------
__global__ void mlp_kernel(const float* __restrict__ surprise,
                           const float* __restrict__ W1, const float* __restrict__ b1,
                           const float* __restrict__ W2, const float* __restrict__ b2)
{
    const int n = blockIdx.x;       // 0..31 memories, 32 = query
    const int t = threadIdx.x;      // 128
    __shared__ float feat[1028];
    __shared__ float hsm[128];
    __shared__ float red[128];

#pragma unroll
    for (int g = 0; g < 8; g++) feat[t + 128 * g] = g_colmean[n * D + t + 128 * g];
    if (t == 0) {
        feat[1024] = (n < NMEM) ? surprise[n] : 0.f;
        feat[1025] = 0.f; feat[1026] = 0.f;
    }
    __syncthreads();

    // layer 1: 8 independent accumulators, 8-way batched loads, rolled outer loop
    float a[8];
    a[0] = b1[t];
#pragma unroll
    for (int j = 1; j < 8; j++) a[j] = 0.f;
#pragma unroll 1
    for (int i = 0; i < 1024; i += 8) {
#pragma unroll
        for (int j = 0; j < 8; j++)
            a[j] = fmaf(feat[i + j], W1[(i + j) * 128 + t], a[j]);
    }
    for (int i = 1024; i < 1027; i++) a[0] = fmaf(feat[i], W1[i * 128 + t], a[0]);
    float acc = ((a[0] + a[1]) + (a[2] + a[3])) + ((a[4] + a[5]) + (a[6] + a[7]));
    hsm[t] = acc > 0.f ? acc : 0.f;
    __syncthreads();

    float nrm = 0.f;
#pragma unroll 1
    for (int g = 0; g < 8; g++) {
        const int d = t + 128 * g;
        float e0 = b2[d], e1 = 0.f, e2 = 0.f, e3 = 0.f;
#pragma unroll 8
        for (int k = 0; k < 128; k += 4) {
            e0 = fmaf(hsm[k + 0], W2[(k + 0) * D + d], e0);
            e1 = fmaf(hsm[k + 1], W2[(k + 1) * D + d], e1);
            e2 = fmaf(hsm[k + 2], W2[(k + 2) * D + d], e2);
            e3 = fmaf(hsm[k + 3], W2[(k + 3) * D + d], e3);
        }
        float e = (e0 + e1) + (e2 + e3);
        g_emb[n * D + d] = e;
        nrm = fmaf(e, e, nrm);
    }
    red[t] = nrm;
    __syncthreads();
#pragma unroll
    for (int off = 64; off; off >>= 1) { if (t < off) red[t] += red[t + off]; __syncthreads(); }
    if (t == 0) g_norm[n] = sqrtf(red[0]);
}

// ---------------- kernel S: sims + rank-ordered top_idx (fp32, 1 block) -------------
__global__ void __launch_bounds__(1024) sims_kernel(const float* __restrict__ pm,
                                                    float* __restrict__ out)
{
    const int t = threadIdx.x, w = t >> 5, l = t & 31;   // w = memory index
    const float4* en = reinterpret_cast<const float4*>(g_emb + (size_t)w * D) + l * 8;
    const float4* eq = reinterpret_cast<const float4*>(g_emb + (size_t)NMEM * D) + l * 8;
    float a0 = 0.f, a1 = 0.f, a2 = 0.f, a3 = 0.f;
#pragma unroll
    for (int j = 0; j < 8; j++) {
        float4 x = en[j], y = eq[j];
        a0 = fmaf(x.x, y.x, a0);
        a1 = fmaf(x.y, y.y, a1);
        a2 = fmaf(x.z, y.z, a2);
        a3 = fmaf(x.w, y.w, a3);
    }
    float p = (a0 + a1) + (a2 + a3);
#pragma unroll
    for (int off = 16; off; off >>= 1) p += __shfl_xor_sync(0xffffffffu, p, off);

    __shared__ float ssim[NMEM];
    if (l == 0) {
        float sim = p / (fmaxf(g_norm[w], 1e-8f) * fmaxf(g_norm[NMEM], 1e-8f)) * pm[w];
        out[(size_t)S * D + w] = sim;
        ssim[w] = sim;
    }
    __syncthreads();
    if (w == 0) {
        const float v = ssim[l];
        int r = 0;
#pragma unroll
        for (int i = 0; i < NMEM; i++) {
            const float vi = ssim[i];
            r += ((vi > v) || (vi == v && i < l)) ? 1 : 0;
        }
        out[(size_t)S * D + NMEM + r] = (float)l;
    }
}

// ---------------- launch ------------------------------------------------------------
extern "C" void kernel_launch(void* const* d_in, const int* in_sizes, int n_in,
                              void* d_out, int out_size)
{
    const float* query    = (const float*)d_in[0];
    const float* memories = (const float*)d_in[1];
    const float* surprise = (const float*)d_in[2];
    const float* pm       = (const float*)d_in[3];
    const float* W1       = (const float*)d_in[4];
    const float* b1       = (const float*)d_in[5];
    const float* W2       = (const float*)d_in[6];
    const float* b2       = (const float*)d_in[7];
    float* out = (float*)d_out;

    // NOTE: no cudaFuncSetAttribute anywhere; all smem static & <= 32KB.

    // 0) agg = query, zero recon region of out
    init_agg_kernel<<<(S * D / 4) / 256, 256>>>(query, out);
    // 1) query column sums (entropy -> g_entropy2 scratch, overwritten later)
    rowstats_kernel<<<RTILES, 128>>>(query, 1, NMEM * RTILES);
    // 2) query colmean (slot 32)
    colmean_kernel<<<1, 256>>>(NMEM);
    // 3) per-memory row entropy + partial colsums (268MB pass)  <- profiled slot
    rowstats_kernel<<<NMEM * RTILES, 128>>>(memories, 0, 0);
    // 4) memory colmeans
    colmean_kernel<<<NMEM, 256>>>(0);
    // 5-6) per-memory top-32 entropy rows
    topk1_kernel<<<NMEM * 8, 32>>>(0);
    topk2_kernel<<<NMEM, 256>>>(0);
    // 7) scatter truncated patches (exact integer fp adds)
    scatter_kernel<<<NMEM * PATCH, 256>>>(memories);
    // 8) row entropy of aggregated
    rowstats_kernel<<<RTILES, 128>>>(nullptr, 1, (NMEM + 1) * RTILES);
    // 9-10) final top-32 rows
    topk1_kernel<<<8, 32>>>(1);
    topk2_kernel<<<1, 256>>>(1);
    // 11) recon rows (trunc(clip(agg/33)))
    recon_kernel<<<PATCH, 256>>>(out);
    // 12) meta-learner embeddings + norms
    mlp_kernel<<<NMEM + 1, 128>>>(surprise, W1, b1, W2, b2);
    // 13) sims + top_idx
    sims_kernel<<<1, 1024>>>(pm, out);
}

// round 8
// speedup vs baseline: 2.8300x; 2.1582x over previous
#include <cuda_runtime.h>
#include <cuda_bf16.h>
#include <float.h>
#include <math.h>

#define S 2048
#define D 1024
#define NMEM 32
#define PATCH 32
#define RTILES 64                 // tiles for big rowstats (32 rows each)

// ---------------- scratch (static device globals; no allocation) ----------------
__device__ float g_entropy [NMEM * S];
__device__ float g_entropy2[S];
__device__ float g_part    [(NMEM + 2) * RTILES * D];   // mem slots 0..2047, query 2048..2111
__device__ float g_colmean [(NMEM + 1) * D];
__device__ float g_agg     [S * D];                     // query + scattered patches (=33*agg)
__device__ float g_h1p     [32 * (NMEM + 1) * 128];     // layer-1 K-split partials
__device__ float g_emb     [(NMEM + 1) * D];
__device__ float g_norm4   [(NMEM + 1) * 4];

// ---------------- cp.async helpers --------------------------------------------------
__device__ __forceinline__ void cp_async16(float* sdst, const float* gsrc)
{
    unsigned sa = (unsigned)__cvta_generic_to_shared(sdst);
    asm volatile("cp.async.cg.shared.global [%0], [%1], 16;" :: "r"(sa), "l"(gsrc) : "memory");
}
__device__ __forceinline__ void issue_chunk(const float* g, float* slot, int l)
{
#pragma unroll
    for (int j = 0; j < 4; j++)
        cp_async16(slot + (l + 32 * j) * 4, g + (l + 32 * j) * 4);
    asm volatile("cp.async.commit_group;" ::: "memory");
}

// ---------------- kernel 1: big pass — row entropy + partial colsums (memories) -----
// grid = NMEM*RTILES, 128 threads (4 warps). Warp w: rows tile*32+w*8..+7 as 16
// half-row 2KB chunks through a 4-slot ring (3 in flight). 32KB static smem.
__global__ void __launch_bounds__(128)
rowstats_kernel(const float* __restrict__ src)
{
    __shared__ float sm[8192];
    const int bx = blockIdx.x;
    const int tile = bx & (RTILES - 1);
    const int n    = bx >> 6;
    const int t = threadIdx.x;
    const int w = t >> 5, l = t & 31;

    const int row0 = tile * 32 + w * 8;
    const float* rowbase = src + (size_t)n * S * D + (size_t)row0 * D;
    float* ring = sm + w * 2048;

    issue_chunk(rowbase + 0,         ring + 0 * 512, l);
    issue_chunk(rowbase + 512,       ring + 1 * 512, l);
    issue_chunk(rowbase + (size_t)D, ring + 2 * 512, l);

    float4 colacc[8];
#pragma unroll
    for (int j = 0; j < 8; j++) colacc[j] = make_float4(0.f, 0.f, 0.f, 0.f);
    float s1[8], s2[8];
#pragma unroll
    for (int k = 0; k < 8; k++) { s1[k] = 0.f; s2[k] = 0.f; }

#pragma unroll
    for (int k = 0; k < 16; k++) {
        if (k <= 13)      asm volatile("cp.async.wait_group 2;" ::: "memory");
        else if (k == 14) asm volatile("cp.async.wait_group 1;" ::: "memory");
        else              asm volatile("cp.async.wait_group 0;" ::: "memory");
        const float4* rp = reinterpret_cast<const float4*>(ring + (k & 3) * 512);
        const int half = k & 1;
        float a = 0.f, b = 0.f;
#pragma unroll
        for (int j = 0; j < 4; j++) {
            float4 x = rp[l + 32 * j];
            const int c = half * 4 + j;
            colacc[c].x += x.x; colacc[c].y += x.y; colacc[c].z += x.z; colacc[c].w += x.w;
            a += (x.x + x.y) + (x.z + x.w);
            b += (x.x * x.x + x.y * x.y) + (x.z * x.z + x.w * x.w);
        }
        s1[k >> 1] += a; s2[k >> 1] += b;
        if (k < 13) {
            const int kn = k + 3;
            issue_chunk(rowbase + (size_t)(kn >> 1) * D + (kn & 1) * 512,
                        ring + (kn & 3) * 512, l);
        }
    }

#pragma unroll
    for (int off = 16; off; off >>= 1) {
#pragma unroll
        for (int k = 0; k < 8; k++) {
            s1[k] += __shfl_xor_sync(0xffffffffu, s1[k], off);
            s2[k] += __shfl_xor_sync(0xffffffffu, s2[k], off);
        }
    }
#pragma unroll
    for (int k = 0; k < 8; k++) {
        if (l == k) {
            float var = (s2[k] - s1[k] * s1[k] * (1.0f / (float)D)) * (1.0f / (float)(D - 1));
            g_entropy[(size_t)n * S + row0 + k] = var > 0.f ? sqrtf(var) : 0.f;
        }
    }

    __syncthreads();
    float* cs = sm;
#pragma unroll
    for (int h = 0; h < 2; h++)
#pragma unroll
        for (int j = 0; j < 4; j++)
            reinterpret_cast<float4*>(&cs[w * 1024 + h * 512 + 4 * (l + 32 * j)])[0]
                = colacc[h * 4 + j];
    __syncthreads();
#pragma unroll
    for (int g = 0; g < 8; g++) {
        const int d = t + 128 * g;
        g_part[(size_t)bx * D + d] = ((cs[0 * 1024 + d] + cs[1 * 1024 + d]) +
                                      (cs[2 * 1024 + d] + cs[3 * 1024 + d]));
    }
}

// ---------------- kernel 0: init — g_agg=query, out=0, query column partials --------
// grid = 64 blocks (32 rows each) x 256 threads (thread = 4 columns)
__global__ void initq_kernel(const float* __restrict__ q, float* __restrict__ out)
{
    const int b = blockIdx.x, t = threadIdx.x;
    float cs0 = 0.f, cs1 = 0.f, cs2 = 0.f, cs3 = 0.f;
    const int row0 = b * 32;
#pragma unroll 4
    for (int r = 0; r < 32; r++) {
        const size_t base = (size_t)(row0 + r) * D;
        float v0 = q[base + t +   0];
        float v1 = q[base + t + 256];
        float v2 = q[base + t + 512];
        float v3 = q[base + t + 768];
        cs0 += v0; cs1 += v1; cs2 += v2; cs3 += v3;
        g_agg[base + t +   0] = v0;  out[base + t +   0] = 0.f;
        g_agg[base + t + 256] = v1;  out[base + t + 256] = 0.f;
        g_agg[base + t + 512] = v2;  out[base + t + 512] = 0.f;
        g_agg[base + t + 768] = v3;  out[base + t + 768] = 0.f;
    }
    const size_t pb = (size_t)(NMEM * RTILES + b) * D;
    g_part[pb + t +   0] = cs0;
    g_part[pb + t + 256] = cs1;
    g_part[pb + t + 512] = cs2;
    g_part[pb + t + 768] = cs3;
}

// ---------------- kernel: colmean — 33 sources x 4 chunks of 256 cols ---------------
__global__ void colmean_kernel()
{
    const int n = blockIdx.x >> 2, c = blockIdx.x & 3;
    const int d = c * 256 + threadIdx.x;
    const size_t base = (size_t)(n * RTILES) * D + d;
    float s = 0.f;
#pragma unroll 8
    for (int p = 0; p < RTILES; p++) s += g_part[base + (size_t)p * D];
    g_colmean[n * D + d] = s * (1.0f / (float)S);
}

// ---------------- shared top-32 block helper (256 threads, 2048 entropies) ----------
// key = (float_bits<<32) | ~loc : u64 max == value desc, then lowest row.
// Result: rows_s[0..31] = selected rows (rank order).
__device__ __forceinline__ void topk_block(const float* __restrict__ e, int* rows_s,
                                           unsigned long long* cand, int t)
{
    const int w = t >> 5, l = t & 31;
    unsigned long long key[8];
#pragma unroll
    for (int j = 0; j < 8; j++) {
        const int loc = w * 256 + l + 32 * j;
        key[j] = ((unsigned long long)__float_as_uint(e[loc]) << 32) | (unsigned)(~loc);
    }
    for (int it = 0; it < 32; it++) {
        unsigned long long m = key[0];
#pragma unroll
        for (int j = 1; j < 8; j++) m = (key[j] > m) ? key[j] : m;
#pragma unroll
        for (int off = 16; off; off >>= 1) {
            unsigned long long o = __shfl_xor_sync(0xffffffffu, m, off);
            m = (o > m) ? o : m;
        }
        if (l == 0) cand[w * 32 + it] = m;
#pragma unroll
        for (int j = 0; j < 8; j++) if (key[j] == m) key[j] = 0ull;
    }
    __syncthreads();
    const unsigned long long k = cand[t];
    int r = 0;
#pragma unroll 8
    for (int i = 0; i < 256; i++) r += (cand[i] > k) ? 1 : 0;
    if (r < PATCH) rows_s[r] = (int)(~(unsigned)k);
    __syncthreads();
}

__device__ __forceinline__ float trunc_clip(float x)
{
    return truncf(fminf(fmaxf(x, -128.f), 127.f));
}

// ---------------- kernel: per-memory top-32 + scatter (fused), 32 blocks x 256 ------
__global__ void __launch_bounds__(256) topk_scatter_kernel(const float* __restrict__ mem)
{
    __shared__ unsigned long long cand[256];
    __shared__ int rows_s[PATCH];
    const int n = blockIdx.x, t = threadIdx.x;
    topk_block(g_entropy + (size_t)n * S, rows_s, cand, t);

    const float* mb = mem + (size_t)n * S * D;
#pragma unroll
    for (int jb = 0; jb < 32; jb += 8) {
        float4 x[8];
#pragma unroll
        for (int j = 0; j < 8; j++)
            x[j] = reinterpret_cast<const float4*>(mb + (size_t)rows_s[jb + j] * D)[t];
#pragma unroll
        for (int j = 0; j < 8; j++) {
            float* dst = g_agg + (size_t)rows_s[jb + j] * D + 4 * t;
            atomicAdd(dst + 0, trunc_clip(x[j].x));
            atomicAdd(dst + 1, trunc_clip(x[j].y));
            atomicAdd(dst + 2, trunc_clip(x[j].z));
            atomicAdd(dst + 3, trunc_clip(x[j].w));
        }
    }
}

// ---------------- kernel: row entropy of g_agg (256 blocks x 8 warps, 1 row/warp) ---
__global__ void __launch_bounds__(256) entropy_agg_kernel()
{
    const int t = threadIdx.x, w = t >> 5, l = t & 31;
    const int row = blockIdx.x * 8 + w;
    const float4* rp = reinterpret_cast<const float4*>(g_agg + (size_t)row * D);
    float a = 0.f, b = 0.f;
#pragma unroll
    for (int j = 0; j < 8; j++) {
        float4 x = rp[l + 32 * j];
        a += (x.x + x.y) + (x.z + x.w);
        b += (x.x * x.x + x.y * x.y) + (x.z * x.z + x.w * x.w);
    }
#pragma unroll
    for (int off = 16; off; off >>= 1) {
        a += __shfl_xor_sync(0xffffffffu, a, off);
        b += __shfl_xor_sync(0xffffffffu, b, off);
    }
    if (l == 0) {
        float var = (b - a * a * (1.0f / (float)D)) * (1.0f / (float)(D - 1));
        g_entropy2[row] = var > 0.f ? sqrtf(var) : 0.f;
    }
}

// ---------------- kernel: final top-32 + recon write (1 block x 256) ----------------
__global__ void __launch_bounds__(256) topk_recon_kernel(float* __restrict__ out)
{
    __shared__ unsigned long long cand[256];
    __shared__ int rows_s[PATCH];
    const int t = threadIdx.x;
    topk_block(g_entropy2, rows_s, cand, t);

    const float inv = 1.0f / 33.0f;
#pragma unroll
    for (int jb = 0; jb < 32; jb += 8) {
        float4 x[8];
#pragma unroll
        for (int j = 0; j < 8; j++)
            x[j] = reinterpret_cast<const float4*>(g_agg + (size_t)rows_s[jb + j] * D)[t];
#pragma unroll
        for (int j = 0; j < 8; j++) {
            float4 r;
            r.x = trunc_clip(x[j].x * inv);
            r.y = trunc_clip(x[j].y * inv);
            r.z = trunc_clip(x[j].z * inv);
            r.w = trunc_clip(x[j].w * inv);
            reinterpret_cast<float4*>(out + (size_t)rows_s[jb + j] * D)[t] = r;
        }
    }
}

// ---------------- kernel: MLP layer 1, K-split GEMM (32 blocks x 128) ---------------
// block b handles W1 rows [b*32, b*32+32); acc over all 33 feature rows.
__global__ void __launch_bounds__(128) mlp1_kernel(const float* __restrict__ W1)
{
    __shared__ float sf[(NMEM + 1) * 32];
    const int b = blockIdx.x, t = threadIdx.x;
    for (int idx = t; idx < (NMEM + 1) * 32; idx += 128) {
        const int n = idx >> 5, kk = idx & 31;
        sf[idx] = g_colmean[n * D + b * 32 + kk];
    }
    __syncthreads();

    float acc[NMEM + 1];
#pragma unroll
    for (int n = 0; n <= NMEM; n++) acc[n] = 0.f;
#pragma unroll 4
    for (int kk = 0; kk < 32; kk++) {
        const float wv = W1[(size_t)(b * 32 + kk) * 128 + t];
#pragma unroll
        for (int n = 0; n <= NMEM; n++) acc[n] = fmaf(sf[n * 32 + kk], wv, acc[n]);
    }
#pragma unroll
    for (int n = 0; n <= NMEM; n++)
        g_h1p[(size_t)(b * (NMEM + 1) + n) * 128 + t] = acc[n];
}

// ---------------- kernel: MLP reduce+ReLU+layer2+norm partials (132 blocks x 256) ---
__global__ void __launch_bounds__(256)
mlp2_kernel(const float* __restrict__ surprise,
            const float* __restrict__ W1, const float* __restrict__ b1,
            const float* __restrict__ W2, const float* __restrict__ b2)
{
    __shared__ float H[128];
    __shared__ float red[8];
    const int n = blockIdx.x >> 2, c = blockIdx.x & 3;
    const int t = threadIdx.x, w = t >> 5, l = t & 31;

    if (t < 128) {
        float h = b1[t];
#pragma unroll 8
        for (int b = 0; b < 32; b++) h += g_h1p[(size_t)(b * (NMEM + 1) + n) * 128 + t];
        if (n < NMEM) h = fmaf(surprise[n], W1[(size_t)1024 * 128 + t], h);
        H[t] = h > 0.f ? h : 0.f;
    }
    __syncthreads();

    const int d = c * 256 + t;
    float e0 = b2[d], e1 = 0.f, e2 = 0.f, e3 = 0.f;
    float e4 = 0.f, e5 = 0.f, e6 = 0.f, e7 = 0.f;
#pragma unroll 4
    for (int k = 0; k < 128; k += 8) {
        e0 = fmaf(H[k + 0], W2[(size_t)(k + 0) * D + d], e0);
        e1 = fmaf(H[k + 1], W2[(size_t)(k + 1) * D + d], e1);
        e2 = fmaf(H[k + 2], W2[(size_t)(k + 2) * D + d], e2);
        e3 = fmaf(H[k + 3], W2[(size_t)(k + 3) * D + d], e3);
        e4 = fmaf(H[k + 4], W2[(size_t)(k + 4) * D + d], e4);
        e5 = fmaf(H[k + 5], W2[(size_t)(k + 5) * D + d], e5);
        e6 = fmaf(H[k + 6], W2[(size_t)(k + 6) * D + d], e6);
        e7 = fmaf(H[k + 7], W2[(size_t)(k + 7) * D + d], e7);
    }
    const float e = ((e0 + e1) + (e2 + e3)) + ((e4 + e5) + (e6 + e7));
    g_emb[(size_t)n * D + d] = e;

    float nrm = e * e;
#pragma unroll
    for (int off = 16; off; off >>= 1) nrm += __shfl_xor_sync(0xffffffffu, nrm, off);
    if (l == 0) red[w] = nrm;
    __syncthreads();
    if (t == 0) {
        float s = ((red[0] + red[1]) + (red[2] + red[3])) +
                  ((red[4] + red[5]) + (red[6] + red[7]));
        g_norm4[n * 4 + c] = s;
    }
}

// ---------------- kernel: sims + rank-ordered top_idx (1 block x 1024) --------------
__global__ void __launch_bounds__(1024) sims_kernel(const float* __restrict__ pm,
                                                    float* __restrict__ out)
{
    const int t = threadIdx.x, w = t >> 5, l = t & 31;   // w = memory index
    const float4* en = reinterpret_cast<const float4*>(g_emb + (size_t)w * D) + l * 8;
    const float4* eq = reinterpret_cast<const float4*>(g_emb + (size_t)NMEM * D) + l * 8;
    float a0 = 0.f, a1 = 0.f, a2 = 0.f, a3 = 0.f;
#pragma unroll
    for (int j = 0; j < 8; j++) {
        float4 x = en[j], y = eq[j];
        a0 = fmaf(x.x, y.x, a0);
        a1 = fmaf(x.y, y.y, a1);
        a2 = fmaf(x.z, y.z, a2);
        a3 = fmaf(x.w, y.w, a3);
    }
    float p = (a0 + a1) + (a2 + a3);
#pragma unroll
    for (int off = 16; off; off >>= 1) p += __shfl_xor_sync(0xffffffffu, p, off);

    __shared__ float ssim[NMEM];
    if (l == 0) {
        const float nn = sqrtf((g_norm4[w * 4 + 0] + g_norm4[w * 4 + 1]) +
                               (g_norm4[w * 4 + 2] + g_norm4[w * 4 + 3]));
        const float nq = sqrtf((g_norm4[NMEM * 4 + 0] + g_norm4[NMEM * 4 + 1]) +
                               (g_norm4[NMEM * 4 + 2] + g_norm4[NMEM * 4 + 3]));
        const float sim = p / (fmaxf(nn, 1e-8f) * fmaxf(nq, 1e-8f)) * pm[w];
        out[(size_t)S * D + w] = sim;
        ssim[w] = sim;
    }
    __syncthreads();
    if (w == 0) {
        const float v = ssim[l];
        int r = 0;
#pragma unroll
        for (int i = 0; i < NMEM; i++) {
            const float vi = ssim[i];
            r += ((vi > v) || (vi == v && i < l)) ? 1 : 0;
        }
        out[(size_t)S * D + NMEM + r] = (float)l;
    }
}

// ---------------- launch ------------------------------------------------------------
extern "C" void kernel_launch(void* const* d_in, const int* in_sizes, int n_in,
                              void* d_out, int out_size)
{
    const float* query    = (const float*)d_in[0];
    const float* memories = (const float*)d_in[1];
    const float* surprise = (const float*)d_in[2];
    const float* pm       = (const float*)d_in[3];
    const float* W1       = (const float*)d_in[4];
    const float* b1       = (const float*)d_in[5];
    const float* W2       = (const float*)d_in[6];
    const float* b2       = (const float*)d_in[7];
    float* out = (float*)d_out;

    // 1) agg = query, zero out[0..S*D), query column partials
    initq_kernel<<<64, 256>>>(query, out);
    // 2) big 268MB pass: per-memory row entropy + column partials
    rowstats_kernel<<<NMEM * RTILES, 128>>>(memories);
    // 3) per-memory top-32 + scatter (fused)
    topk_scatter_kernel<<<NMEM, 256>>>(memories);
    // 4) row entropy of aggregated
    entropy_agg_kernel<<<256, 256>>>();
    // 5) final top-32 + recon write (fused)
    topk_recon_kernel<<<1, 256>>>(out);
    // 6) column means (33 sources x 4 chunks)
    colmean_kernel<<<(NMEM + 1) * 4, 256>>>();
    // 7) MLP layer 1 (K-split GEMM)
    mlp1_kernel<<<32, 128>>>(W1);
    // 8) MLP reduce + ReLU + layer 2 + norm partials
    mlp2_kernel<<<(NMEM + 1) * 4, 256>>>(surprise, W1, b1, W2, b2);
    // 9) sims + top_idx
    sims_kernel<<<1, 1024>>>(pm, out);
}

// round 9
// speedup vs baseline: 3.5353x; 1.2492x over previous
#include <cuda_runtime.h>
#include <cuda_bf16.h>
#include <float.h>
#include <math.h>

#define S 2048
#define D 1024
#define NMEM 32
#define PATCH 32
#define RTILES 64                 // tiles per memory for big rowstats (32 rows each)

// ---------------- scratch (static device globals; no allocation) ----------------
__device__ float g_entropy [NMEM * S];
__device__ float g_entropy2[S];
__device__ float g_part    [(NMEM + 1) * RTILES * D];   // slots n*64+p (query: 2048+p)
__device__ float g_agg     [S * D];                     // query + patches (= 33*aggregated)
__device__ float g_h1p     [32 * (NMEM + 1) * 128];     // layer-1 K-split partials
__device__ float g_emb     [(NMEM + 1) * D];
__device__ float g_norm4   [(NMEM + 1) * 4];
__device__ unsigned g_cnt = 0;
__device__ volatile unsigned g_gen;                     // monotonically increasing

// ---------------- cp.async helpers --------------------------------------------------
__device__ __forceinline__ void cp_async16(float* sdst, const float* gsrc)
{
    unsigned sa = (unsigned)__cvta_generic_to_shared(sdst);
    asm volatile("cp.async.cg.shared.global [%0], [%1], 16;" :: "r"(sa), "l"(gsrc) : "memory");
}
__device__ __forceinline__ void issue_chunk(const float* g, float* slot, int l)
{
#pragma unroll
    for (int j = 0; j < 4; j++)
        cp_async16(slot + (l + 32 * j) * 4, g + (l + 32 * j) * 4);
    asm volatile("cp.async.commit_group;" ::: "memory");
}

// =====================================================================================
// K0: fused big pass. Blocks 0..2047: memory row entropy + column partials.
//     Blocks 2048..2111: query -> g_agg copy, out zero, query column partials.
// 128 threads/block, 32KB static smem (only used by memory blocks).
// =====================================================================================
__global__ void __launch_bounds__(128)
bigpass_kernel(const float* __restrict__ mem, const float* __restrict__ q,
               float* __restrict__ out)
{
    __shared__ float sm[8192];
    const int bx = blockIdx.x;
    const int t = threadIdx.x;
    const int w = t >> 5, l = t & 31;

    if (bx < NMEM * RTILES) {
        const int tile = bx & (RTILES - 1);
        const int n    = bx >> 6;
        const int row0 = tile * 32 + w * 8;
        const float* rowbase = mem + (size_t)n * S * D + (size_t)row0 * D;
        float* ring = sm + w * 2048;

        issue_chunk(rowbase + 0,         ring + 0 * 512, l);
        issue_chunk(rowbase + 512,       ring + 1 * 512, l);
        issue_chunk(rowbase + (size_t)D, ring + 2 * 512, l);

        float4 colacc[8];
#pragma unroll
        for (int j = 0; j < 8; j++) colacc[j] = make_float4(0.f, 0.f, 0.f, 0.f);
        float s1[8], s2[8];
#pragma unroll
        for (int k = 0; k < 8; k++) { s1[k] = 0.f; s2[k] = 0.f; }

#pragma unroll
        for (int k = 0; k < 16; k++) {
            if (k <= 13)      asm volatile("cp.async.wait_group 2;" ::: "memory");
            else if (k == 14) asm volatile("cp.async.wait_group 1;" ::: "memory");
            else              asm volatile("cp.async.wait_group 0;" ::: "memory");
            const float4* rp = reinterpret_cast<const float4*>(ring + (k & 3) * 512);
            const int half = k & 1;
            float a = 0.f, b = 0.f;
#pragma unroll
            for (int j = 0; j < 4; j++) {
                float4 x = rp[l + 32 * j];
                const int c = half * 4 + j;
                colacc[c].x += x.x; colacc[c].y += x.y; colacc[c].z += x.z; colacc[c].w += x.w;
                a += (x.x + x.y) + (x.z + x.w);
                b += (x.x * x.x + x.y * x.y) + (x.z * x.z + x.w * x.w);
            }
            s1[k >> 1] += a; s2[k >> 1] += b;
            if (k < 13) {
                const int kn = k + 3;
                issue_chunk(rowbase + (size_t)(kn >> 1) * D + (kn & 1) * 512,
                            ring + (kn & 3) * 512, l);
            }
        }

#pragma unroll
        for (int off = 16; off; off >>= 1) {
#pragma unroll
            for (int k = 0; k < 8; k++) {
                s1[k] += __shfl_xor_sync(0xffffffffu, s1[k], off);
                s2[k] += __shfl_xor_sync(0xffffffffu, s2[k], off);
            }
        }
#pragma unroll
        for (int k = 0; k < 8; k++) {
            if (l == k) {
                float var = (s2[k] - s1[k] * s1[k] * (1.0f / (float)D)) * (1.0f / (float)(D - 1));
                g_entropy[(size_t)n * S + row0 + k] = var > 0.f ? sqrtf(var) : 0.f;
            }
        }

        __syncthreads();
        float* cs = sm;
#pragma unroll
        for (int h = 0; h < 2; h++)
#pragma unroll
            for (int j = 0; j < 4; j++)
                reinterpret_cast<float4*>(&cs[w * 1024 + h * 512 + 4 * (l + 32 * j)])[0]
                    = colacc[h * 4 + j];
        __syncthreads();
#pragma unroll
        for (int g = 0; g < 8; g++) {
            const int d = t + 128 * g;
            g_part[(size_t)bx * D + d] = ((cs[0 * 1024 + d] + cs[1 * 1024 + d]) +
                                          (cs[2 * 1024 + d] + cs[3 * 1024 + d]));
        }
    } else {
        // query init block: 32 rows, copy to g_agg, zero out, accumulate column sums
        const int qb = bx - NMEM * RTILES;        // 0..63
        const int row0 = qb * 32;
        float cs[8];
#pragma unroll
        for (int g = 0; g < 8; g++) cs[g] = 0.f;
#pragma unroll 2
        for (int r = 0; r < 32; r++) {
            const size_t base = (size_t)(row0 + r) * D;
#pragma unroll
            for (int g = 0; g < 8; g++) {
                const int d = t + 128 * g;
                float v = q[base + d];
                cs[g] += v;
                g_agg[base + d] = v;
                out[base + d] = 0.f;
            }
        }
        const size_t pb = (size_t)(NMEM * RTILES + qb) * D;
#pragma unroll
        for (int g = 0; g < 8; g++) g_part[pb + t + 128 * g] = cs[g];
    }
}

// =====================================================================================
// K1: mega-tail with software grid barriers (grid = 264 blocks x 256 threads;
//     co-residency: 264 << capacity, so spin barrier is safe).
// =====================================================================================
__device__ __forceinline__ void grid_barrier()
{
    __threadfence();
    __syncthreads();
    if (threadIdx.x == 0) {
        const unsigned gen0 = g_gen;
        __threadfence();
        if (atomicAdd(&g_cnt, 1) == gridDim.x - 1) {
            atomicExch(&g_cnt, 0);
            __threadfence();
            atomicAdd((unsigned*)&g_gen, 1);
        } else {
            while (g_gen == gen0) { __nanosleep(64); }
        }
    }
    __syncthreads();
    __threadfence();
}

// top-32 of 2048 entropies (256 threads). key = (bits<<32)|~loc -> value desc, low idx.
__device__ __forceinline__ void topk_block(const float* __restrict__ e, int* rows_s,
                                           unsigned long long* cand, int t)
{
    const int w = t >> 5, l = t & 31;
    unsigned long long key[8];
#pragma unroll
    for (int j = 0; j < 8; j++) {
        const int loc = w * 256 + l + 32 * j;
        key[j] = ((unsigned long long)__float_as_uint(e[loc]) << 32) | (unsigned)(~loc);
    }
    for (int it = 0; it < 32; it++) {
        unsigned long long m = key[0];
#pragma unroll
        for (int j = 1; j < 8; j++) m = (key[j] > m) ? key[j] : m;
#pragma unroll
        for (int off = 16; off; off >>= 1) {
            unsigned long long o = __shfl_xor_sync(0xffffffffu, m, off);
            m = (o > m) ? o : m;
        }
        if (l == 0) cand[w * 32 + it] = m;
#pragma unroll
        for (int j = 0; j < 8; j++) if (key[j] == m) key[j] = 0ull;
    }
    __syncthreads();
    const unsigned long long k = cand[t];
    int r = 0;
#pragma unroll 8
    for (int i = 0; i < 256; i++) r += (cand[i] > k) ? 1 : 0;
    if (r < PATCH) rows_s[r] = (int)(~(unsigned)k);
    __syncthreads();
}

__device__ __forceinline__ float trunc_clip(float x)
{
    return truncf(fminf(fmaxf(x, -128.f), 127.f));
}

__global__ void __launch_bounds__(256)
tail_kernel(const float* __restrict__ mem, const float* __restrict__ surprise,
            const float* __restrict__ pm,
            const float* __restrict__ W1, const float* __restrict__ b1,
            const float* __restrict__ W2, const float* __restrict__ b2,
            float* __restrict__ out)
{
    __shared__ unsigned long long cand[256];
    __shared__ int rows_s[PATCH];
    __shared__ float sf[(NMEM + 1) * 32];
    __shared__ float H[128];
    __shared__ float ssim[NMEM];

    const int b = blockIdx.x, t = threadIdx.x;
    const int w = t >> 5, l = t & 31;

    // ---------------- Phase A ----------------
    if (b < 32) {
        // per-memory top-32 + scatter into g_agg
        const int n = b;
        topk_block(g_entropy + (size_t)n * S, rows_s, cand, t);
        const float* mb = mem + (size_t)n * S * D;
#pragma unroll
        for (int jb = 0; jb < 32; jb += 8) {
            float4 x[8];
#pragma unroll
            for (int j = 0; j < 8; j++)
                x[j] = reinterpret_cast<const float4*>(mb + (size_t)rows_s[jb + j] * D)[t];
#pragma unroll
            for (int j = 0; j < 8; j++) {
                float* dst = g_agg + (size_t)rows_s[jb + j] * D + 4 * t;
                atomicAdd(dst + 0, trunc_clip(x[j].x));
                atomicAdd(dst + 1, trunc_clip(x[j].y));
                atomicAdd(dst + 2, trunc_clip(x[j].z));
                atomicAdd(dst + 3, trunc_clip(x[j].w));
            }
        }
    } else if (b < 64) {
        // mlp1 chunk c: inline colmean for cols [c*32, c*32+32), then K-split GEMM
        const int c = b - 32;
        for (int idx = t; idx < (NMEM + 1) * 32; idx += 256) {
            const int n = idx >> 5, kk = idx & 31;
            const size_t base = (size_t)(n * RTILES) * D + c * 32 + kk;
            float s = 0.f;
#pragma unroll 8
            for (int p = 0; p < RTILES; p++) s += g_part[base + (size_t)p * D];
            sf[idx] = s * (1.0f / (float)S);
        }
        __syncthreads();
        if (t < 128) {
            float acc[NMEM + 1];
#pragma unroll
            for (int n = 0; n <= NMEM; n++) acc[n] = 0.f;
#pragma unroll 4
            for (int kk = 0; kk < 32; kk++) {
                const float wv = W1[(size_t)(c * 32 + kk) * 128 + t];
#pragma unroll
                for (int n = 0; n <= NMEM; n++) acc[n] = fmaf(sf[n * 32 + kk], wv, acc[n]);
            }
#pragma unroll
            for (int n = 0; n <= NMEM; n++)
                g_h1p[(size_t)(c * (NMEM + 1) + n) * 128 + t] = acc[n];
        }
    }

    grid_barrier();

    // ---------------- Phase B ----------------
    if (b < 128) {
        // entropy of 16 agg rows (8 warps x 2 rows)
#pragma unroll
        for (int r = 0; r < 2; r++) {
            const int row = b * 16 + w * 2 + r;
            const float4* rp = reinterpret_cast<const float4*>(g_agg + (size_t)row * D);
            float a = 0.f, bb = 0.f;
#pragma unroll
            for (int j = 0; j < 8; j++) {
                float4 x = rp[l + 32 * j];
                a += (x.x + x.y) + (x.z + x.w);
                bb += (x.x * x.x + x.y * x.y) + (x.z * x.z + x.w * x.w);
            }
#pragma unroll
            for (int off = 16; off; off >>= 1) {
                a += __shfl_xor_sync(0xffffffffu, a, off);
                bb += __shfl_xor_sync(0xffffffffu, bb, off);
            }
            if (l == 0) {
                float var = (bb - a * a * (1.0f / (float)D)) * (1.0f / (float)(D - 1));
                g_entropy2[row] = var > 0.f ? sqrtf(var) : 0.f;
            }
        }
    } else if (b >= 132) {
        // mlp2: reduce h1 partials + ReLU + layer 2 + norm partials
        const int m = b - 132;                 // 0..131
        const int n = m >> 2, c = m & 3;
        if (t < 128) {
            float h = b1[t];
#pragma unroll 8
            for (int cc = 0; cc < 32; cc++)
                h += g_h1p[(size_t)(cc * (NMEM + 1) + n) * 128 + t];
            if (n < NMEM) h = fmaf(surprise[n], W1[(size_t)1024 * 128 + t], h);
            H[t] = h > 0.f ? h : 0.f;
        }
        __syncthreads();
        const int d = c * 256 + t;
        float e0 = b2[d], e1 = 0.f, e2 = 0.f, e3 = 0.f;
        float e4 = 0.f, e5 = 0.f, e6 = 0.f, e7 = 0.f;
#pragma unroll 4
        for (int k = 0; k < 128; k += 8) {
            e0 = fmaf(H[k + 0], W2[(size_t)(k + 0) * D + d], e0);
            e1 = fmaf(H[k + 1], W2[(size_t)(k + 1) * D + d], e1);
            e2 = fmaf(H[k + 2], W2[(size_t)(k + 2) * D + d], e2);
            e3 = fmaf(H[k + 3], W2[(size_t)(k + 3) * D + d], e3);
            e4 = fmaf(H[k + 4], W2[(size_t)(k + 4) * D + d], e4);
            e5 = fmaf(H[k + 5], W2[(size_t)(k + 5) * D + d], e5);
            e6 = fmaf(H[k + 6], W2[(size_t)(k + 6) * D + d], e6);
            e7 = fmaf(H[k + 7], W2[(size_t)(k + 7) * D + d], e7);
        }
        const float e = ((e0 + e1) + (e2 + e3)) + ((e4 + e5) + (e6 + e7));
        g_emb[(size_t)n * D + d] = e;
        float nrm = e * e;
#pragma unroll
        for (int off = 16; off; off >>= 1) nrm += __shfl_xor_sync(0xffffffffu, nrm, off);
        __syncthreads();                       // reuse H as reduction scratch
        if (l == 0) H[w] = nrm;
        __syncthreads();
        if (t == 0) {
            float s = ((H[0] + H[1]) + (H[2] + H[3])) + ((H[4] + H[5]) + (H[6] + H[7]));
            g_norm4[n * 4 + c] = s;
        }
    }

    grid_barrier();

    // ---------------- Phase C ----------------
    if (b == 0) {
        // final top-32 + recon rows
        topk_block(g_entropy2, rows_s, cand, t);
        const float inv = 1.0f / 33.0f;
#pragma unroll
        for (int jb = 0; jb < 32; jb += 8) {
            float4 x[8];
#pragma unroll
            for (int j = 0; j < 8; j++)
                x[j] = reinterpret_cast<const float4*>(g_agg + (size_t)rows_s[jb + j] * D)[t];
#pragma unroll
            for (int j = 0; j < 8; j++) {
                float4 r;
                r.x = trunc_clip(x[j].x * inv);
                r.y = trunc_clip(x[j].y * inv);
                r.z = trunc_clip(x[j].z * inv);
                r.w = trunc_clip(x[j].w * inv);
                reinterpret_cast<float4*>(out + (size_t)rows_s[jb + j] * D)[t] = r;
            }
        }
    } else if (b == 1) {
        // sims + rank-ordered top_idx (warp w handles memories w, w+8, w+16, w+24)
        const float nq = sqrtf((g_norm4[NMEM * 4 + 0] + g_norm4[NMEM * 4 + 1]) +
                               (g_norm4[NMEM * 4 + 2] + g_norm4[NMEM * 4 + 3]));
#pragma unroll
        for (int mi = 0; mi < 4; mi++) {
            const int n = w + 8 * mi;
            const float4* en = reinterpret_cast<const float4*>(g_emb + (size_t)n * D) + l * 8;
            const float4* eq = reinterpret_cast<const float4*>(g_emb + (size_t)NMEM * D) + l * 8;
            float a0 = 0.f, a1 = 0.f, a2 = 0.f, a3 = 0.f;
#pragma unroll
            for (int j = 0; j < 8; j++) {
                float4 x = en[j], y = eq[j];
                a0 = fmaf(x.x, y.x, a0);
                a1 = fmaf(x.y, y.y, a1);
                a2 = fmaf(x.z, y.z, a2);
                a3 = fmaf(x.w, y.w, a3);
            }
            float p = (a0 + a1) + (a2 + a3);
#pragma unroll
            for (int off = 16; off; off >>= 1) p += __shfl_xor_sync(0xffffffffu, p, off);
            if (l == 0) {
                const float nn = sqrtf((g_norm4[n * 4 + 0] + g_norm4[n * 4 + 1]) +
                                       (g_norm4[n * 4 + 2] + g_norm4[n * 4 + 3]));
                const float sim = p / (fmaxf(nn, 1e-8f) * fmaxf(nq, 1e-8f)) * pm[n];
                out[(size_t)S * D + n] = sim;
                ssim[n] = sim;
            }
        }
        __syncthreads();
        if (t < NMEM) {
            const float v = ssim[t];
            int r = 0;
#pragma unroll
            for (int i = 0; i < NMEM; i++) {
                const float vi = ssim[i];
                r += ((vi > v) || (vi == v && i < t)) ? 1 : 0;
            }
            out[(size_t)S * D + NMEM + r] = (float)t;
        }
    }
}

// ---------------- launch ------------------------------------------------------------
extern "C" void kernel_launch(void* const* d_in, const int* in_sizes, int n_in,
                              void* d_out, int out_size)
{
    const float* query    = (const float*)d_in[0];
    const float* memories = (const float*)d_in[1];
    const float* surprise = (const float*)d_in[2];
    const float* pm       = (const float*)d_in[3];
    const float* W1       = (const float*)d_in[4];
    const float* b1       = (const float*)d_in[5];
    const float* W2       = (const float*)d_in[6];
    const float* b2       = (const float*)d_in[7];
    float* out = (float*)d_out;

    // K0: 268MB memory pass + query init (2048 + 64 blocks)
    bigpass_kernel<<<NMEM * RTILES + 64, 128>>>(memories, query, out);
    // K1: everything else in one kernel with grid barriers
    tail_kernel<<<264, 256>>>(memories, surprise, pm, W1, b1, W2, b2, out);
}

// round 10
// speedup vs baseline: 3.5746x; 1.0111x over previous
#include <cuda_runtime.h>
#include <cuda_bf16.h>
#include <float.h>
#include <math.h>

#define S 2048
#define D 1024
#define NMEM 32
#define PATCH 32
#define RTILES 64                 // tiles per memory for big rowstats (32 rows each)
#define TAILB 164                 // tail grid

// ---------------- scratch (static device globals; no allocation) ----------------
__device__ float g_entropy [NMEM * S];
__device__ float g_entropy2[S];
__device__ float g_part    [(NMEM + 1) * RTILES * D];   // slot n*64+p (query n=32)
__device__ float g_colmean [(NMEM + 1) * D];
__device__ float g_agg     [S * D];                     // query + patches (= 33*aggregated)
__device__ float g_h1p     [32 * (NMEM + 1) * 128];     // layer-1 K-split partials
__device__ float g_emb     [(NMEM + 1) * D];
__device__ float g_norm4   [(NMEM + 1) * 4];
__device__ int   g_fidx    [PATCH];
__device__ float g_wsink;
__device__ unsigned g_cnt = 0;
__device__ volatile unsigned g_gen;

// ---------------- cp.async helpers --------------------------------------------------
__device__ __forceinline__ void cp_async16(float* sdst, const float* gsrc)
{
    unsigned sa = (unsigned)__cvta_generic_to_shared(sdst);
    asm volatile("cp.async.cg.shared.global [%0], [%1], 16;" :: "r"(sa), "l"(gsrc) : "memory");
}
__device__ __forceinline__ void issue_chunk(const float* g, float* slot, int l)
{
#pragma unroll
    for (int j = 0; j < 4; j++)
        cp_async16(slot + (l + 32 * j) * 4, g + (l + 32 * j) * 4);
    asm volatile("cp.async.commit_group;" ::: "memory");
}

// =====================================================================================
// K0: fused big pass (unchanged: at LTS-cap roofline).
// Blocks 0..2047: memory row entropy + column partials.
// Blocks 2048..2111: query -> g_agg copy, out zero, query column partials.
// =====================================================================================
__global__ void __launch_bounds__(128)
bigpass_kernel(const float* __restrict__ mem, const float* __restrict__ q,
               float* __restrict__ out)
{
    __shared__ float sm[8192];
    const int bx = blockIdx.x;
    const int t = threadIdx.x;
    const int w = t >> 5, l = t & 31;

    if (bx < NMEM * RTILES) {
        const int tile = bx & (RTILES - 1);
        const int n    = bx >> 6;
        const int row0 = tile * 32 + w * 8;
        const float* rowbase = mem + (size_t)n * S * D + (size_t)row0 * D;
        float* ring = sm + w * 2048;

        issue_chunk(rowbase + 0,         ring + 0 * 512, l);
        issue_chunk(rowbase + 512,       ring + 1 * 512, l);
        issue_chunk(rowbase + (size_t)D, ring + 2 * 512, l);

        float4 colacc[8];
#pragma unroll
        for (int j = 0; j < 8; j++) colacc[j] = make_float4(0.f, 0.f, 0.f, 0.f);
        float s1[8], s2[8];
#pragma unroll
        for (int k = 0; k < 8; k++) { s1[k] = 0.f; s2[k] = 0.f; }

#pragma unroll
        for (int k = 0; k < 16; k++) {
            if (k <= 13)      asm volatile("cp.async.wait_group 2;" ::: "memory");
            else if (k == 14) asm volatile("cp.async.wait_group 1;" ::: "memory");
            else              asm volatile("cp.async.wait_group 0;" ::: "memory");
            const float4* rp = reinterpret_cast<const float4*>(ring + (k & 3) * 512);
            const int half = k & 1;
            float a = 0.f, b = 0.f;
#pragma unroll
            for (int j = 0; j < 4; j++) {
                float4 x = rp[l + 32 * j];
                const int c = half * 4 + j;
                colacc[c].x += x.x; colacc[c].y += x.y; colacc[c].z += x.z; colacc[c].w += x.w;
                a += (x.x + x.y) + (x.z + x.w);
                b += (x.x * x.x + x.y * x.y) + (x.z * x.z + x.w * x.w);
            }
            s1[k >> 1] += a; s2[k >> 1] += b;
            if (k < 13) {
                const int kn = k + 3;
                issue_chunk(rowbase + (size_t)(kn >> 1) * D + (kn & 1) * 512,
                            ring + (kn & 3) * 512, l);
            }
        }

#pragma unroll
        for (int off = 16; off; off >>= 1) {
#pragma unroll
            for (int k = 0; k < 8; k++) {
                s1[k] += __shfl_xor_sync(0xffffffffu, s1[k], off);
                s2[k] += __shfl_xor_sync(0xffffffffu, s2[k], off);
            }
        }
#pragma unroll
        for (int k = 0; k < 8; k++) {
            if (l == k) {
                float var = (s2[k] - s1[k] * s1[k] * (1.0f / (float)D)) * (1.0f / (float)(D - 1));
                g_entropy[(size_t)n * S + row0 + k] = var > 0.f ? sqrtf(var) : 0.f;
            }
        }

        __syncthreads();
        float* cs = sm;
#pragma unroll
        for (int h = 0; h < 2; h++)
#pragma unroll
            for (int j = 0; j < 4; j++)
                reinterpret_cast<float4*>(&cs[w * 1024 + h * 512 + 4 * (l + 32 * j)])[0]
                    = colacc[h * 4 + j];
        __syncthreads();
#pragma unroll
        for (int g = 0; g < 8; g++) {
            const int d = t + 128 * g;
            g_part[(size_t)bx * D + d] = ((cs[0 * 1024 + d] + cs[1 * 1024 + d]) +
                                          (cs[2 * 1024 + d] + cs[3 * 1024 + d]));
        }
    } else {
        const int qb = bx - NMEM * RTILES;        // 0..63
        const int row0 = qb * 32;
        float cs[8];
#pragma unroll
        for (int g = 0; g < 8; g++) cs[g] = 0.f;
#pragma unroll 2
        for (int r = 0; r < 32; r++) {
            const size_t base = (size_t)(row0 + r) * D;
#pragma unroll
            for (int g = 0; g < 8; g++) {
                const int d = t + 128 * g;
                float v = q[base + d];
                cs[g] += v;
                g_agg[base + d] = v;
                out[base + d] = 0.f;
            }
        }
        const size_t pb = (size_t)(NMEM * RTILES + qb) * D;
#pragma unroll
        for (int g = 0; g < 8; g++) g_part[pb + t + 128 * g] = cs[g];
    }
}

// =====================================================================================
// K1: mega-tail, 164 blocks x 256 threads, 3 software grid barriers.
// =====================================================================================
__device__ __forceinline__ void grid_barrier()
{
    __threadfence();
    __syncthreads();
    if (threadIdx.x == 0) {
        const unsigned gen0 = g_gen;
        __threadfence();
        if (atomicAdd(&g_cnt, 1) == gridDim.x - 1) {
            atomicExch(&g_cnt, 0);
            __threadfence();
            atomicAdd((unsigned*)&g_gen, 1);
        } else {
            while (g_gen == gen0) { __nanosleep(64); }
        }
    }
    __syncthreads();
    __threadfence();
}

// top-32 of 2048 entropies (256 threads). key = (bits<<32)|~loc -> value desc, low idx.
__device__ __forceinline__ void topk_block(const float* __restrict__ e, int* rows_s,
                                           unsigned long long* cand, int t)
{
    const int w = t >> 5, l = t & 31;
    unsigned long long key[8];
#pragma unroll
    for (int j = 0; j < 8; j++) {
        const int loc = w * 256 + l + 32 * j;
        key[j] = ((unsigned long long)__float_as_uint(e[loc]) << 32) | (unsigned)(~loc);
    }
    for (int it = 0; it < 32; it++) {
        unsigned long long m = key[0];
#pragma unroll
        for (int j = 1; j < 8; j++) m = (key[j] > m) ? key[j] : m;
#pragma unroll
        for (int off = 16; off; off >>= 1) {
            unsigned long long o = __shfl_xor_sync(0xffffffffu, m, off);
            m = (o > m) ? o : m;
        }
        if (l == 0) cand[w * 32 + it] = m;
#pragma unroll
        for (int j = 0; j < 8; j++) if (key[j] == m) key[j] = 0ull;
    }
    __syncthreads();
    const unsigned long long k = cand[t];
    int r = 0;
#pragma unroll 8
    for (int i = 0; i < 256; i++) r += (cand[i] > k) ? 1 : 0;
    if (r < PATCH) rows_s[r] = (int)(~(unsigned)k);
    __syncthreads();
}

__device__ __forceinline__ float trunc_clip(float x)
{
    return truncf(fminf(fmaxf(x, -128.f), 127.f));
}

__global__ void __launch_bounds__(256)
tail_kernel(const float* __restrict__ mem, const float* __restrict__ surprise,
            const float* __restrict__ pm,
            const float* __restrict__ W1, const float* __restrict__ b1,
            const float* __restrict__ W2, const float* __restrict__ b2,
            float* __restrict__ out)
{
    __shared__ unsigned long long cand[256];
    __shared__ int rows_s[PATCH];
    __shared__ float sf[(NMEM + 1) * 32];
    __shared__ float H[128];
    __shared__ float ssim[NMEM];

    const int b = blockIdx.x, t = threadIdx.x;
    const int w = t >> 5, l = t & 31;

    // ============ Phase A: topk+scatter (0..31) | colmean (32..97) | warm (98..163) ==
    if (b < 32) {
        const int n = b;
        topk_block(g_entropy + (size_t)n * S, rows_s, cand, t);
        const float* mb = mem + (size_t)n * S * D;
#pragma unroll
        for (int jb = 0; jb < 32; jb += 8) {
            float4 x[8];
#pragma unroll
            for (int j = 0; j < 8; j++)
                x[j] = reinterpret_cast<const float4*>(mb + (size_t)rows_s[jb + j] * D)[t];
#pragma unroll
            for (int j = 0; j < 8; j++) {
                float* dst = g_agg + (size_t)rows_s[jb + j] * D + 4 * t;
                atomicAdd(dst + 0, trunc_clip(x[j].x));
                atomicAdd(dst + 1, trunc_clip(x[j].y));
                atomicAdd(dst + 2, trunc_clip(x[j].z));
                atomicAdd(dst + 3, trunc_clip(x[j].w));
            }
        }
    } else if (b < 98) {
        // coalesced colmean: block handles source n, half "hf" (512 cols = 2 chunks)
        const int m = b - 32;                // 0..65
        const int n = m >> 1, hf = m & 1;
#pragma unroll
        for (int g = 0; g < 2; g++) {
            const int d = hf * 512 + g * 256 + t;
            const size_t base = (size_t)(n * RTILES) * D + d;
            float s = 0.f;
#pragma unroll 8
            for (int p = 0; p < RTILES; p++) s += g_part[base + (size_t)p * D];
            g_colmean[(size_t)n * D + d] = s * (1.0f / (float)S);
        }
    } else {
        // warm W1 + W2 into L2 (1MB total over 66 blocks)
        const int j = b - 98;                // 0..65
        float acc = 0.f;
        for (int i = j * 256 + t; i < 1027 * 128; i += 66 * 256) acc += W1[i];
        for (int i = j * 256 + t; i < 128 * D;    i += 66 * 256) acc += W2[i];
        if (acc == 1.2345678e30f) g_wsink = acc;   // never true; defeats DCE
    }

    grid_barrier();

    // ============ Phase B: entropy_agg (0..127) | mlp1 (128..159) ====================
    if (b < 128) {
#pragma unroll
        for (int r = 0; r < 2; r++) {
            const int row = b * 16 + w * 2 + r;
            const float4* rp = reinterpret_cast<const float4*>(g_agg + (size_t)row * D);
            float a = 0.f, bb = 0.f;
#pragma unroll
            for (int j = 0; j < 8; j++) {
                float4 x = rp[l + 32 * j];
                a += (x.x + x.y) + (x.z + x.w);
                bb += (x.x * x.x + x.y * x.y) + (x.z * x.z + x.w * x.w);
            }
#pragma unroll
            for (int off = 16; off; off >>= 1) {
                a += __shfl_xor_sync(0xffffffffu, a, off);
                bb += __shfl_xor_sync(0xffffffffu, bb, off);
            }
            if (l == 0) {
                float var = (bb - a * a * (1.0f / (float)D)) * (1.0f / (float)(D - 1));
                g_entropy2[row] = var > 0.f ? sqrtf(var) : 0.f;
            }
        }
    } else if (b < 160) {
        // mlp1 K-chunk c: W1 rows [c*32, c*32+32), all 33 feature rows
        const int c = b - 128;
        for (int idx = t; idx < (NMEM + 1) * 32; idx += 256) {
            const int n = idx >> 5, kk = idx & 31;
            sf[idx] = g_colmean[(size_t)n * D + c * 32 + kk];
        }
        __syncthreads();
        if (t < 128) {
            float acc[NMEM + 1];
#pragma unroll
            for (int n = 0; n <= NMEM; n++) acc[n] = 0.f;
#pragma unroll 4
            for (int kk = 0; kk < 32; kk++) {
                const float wv = W1[(size_t)(c * 32 + kk) * 128 + t];
#pragma unroll
                for (int n = 0; n <= NMEM; n++) acc[n] = fmaf(sf[n * 32 + kk], wv, acc[n]);
            }
#pragma unroll
            for (int n = 0; n <= NMEM; n++)
                g_h1p[(size_t)(c * (NMEM + 1) + n) * 128 + t] = acc[n];
        }
    }

    grid_barrier();

    // ============ Phase C: mlp2 (0..131) | final topk (132) ==========================
    if (b < 132) {
        const int n = b >> 2, c = b & 3;
        if (t < 128) {
            float h = b1[t];
#pragma unroll 8
            for (int cc = 0; cc < 32; cc++)
                h += g_h1p[(size_t)(cc * (NMEM + 1) + n) * 128 + t];
            if (n < NMEM) h = fmaf(surprise[n], W1[(size_t)1024 * 128 + t], h);
            H[t] = h > 0.f ? h : 0.f;
        }
        __syncthreads();
        const int d = c * 256 + t;
        float e0 = b2[d], e1 = 0.f, e2 = 0.f, e3 = 0.f;
        float e4 = 0.f, e5 = 0.f, e6 = 0.f, e7 = 0.f;
#pragma unroll 4
        for (int k = 0; k < 128; k += 8) {
            e0 = fmaf(H[k + 0], W2[(size_t)(k + 0) * D + d], e0);
            e1 = fmaf(H[k + 1], W2[(size_t)(k + 1) * D + d], e1);
            e2 = fmaf(H[k + 2], W2[(size_t)(k + 2) * D + d], e2);
            e3 = fmaf(H[k + 3], W2[(size_t)(k + 3) * D + d], e3);
            e4 = fmaf(H[k + 4], W2[(size_t)(k + 4) * D + d], e4);
            e5 = fmaf(H[k + 5], W2[(size_t)(k + 5) * D + d], e5);
            e6 = fmaf(H[k + 6], W2[(size_t)(k + 6) * D + d], e6);
            e7 = fmaf(H[k + 7], W2[(size_t)(k + 7) * D + d], e7);
        }
        const float e = ((e0 + e1) + (e2 + e3)) + ((e4 + e5) + (e6 + e7));
        g_emb[(size_t)n * D + d] = e;
        float nrm = e * e;
#pragma unroll
        for (int off = 16; off; off >>= 1) nrm += __shfl_xor_sync(0xffffffffu, nrm, off);
        __syncthreads();                    // reuse H as reduction scratch
        if (l == 0) H[w] = nrm;
        __syncthreads();
        if (t == 0)
            g_norm4[n * 4 + c] = ((H[0] + H[1]) + (H[2] + H[3])) +
                                 ((H[4] + H[5]) + (H[6] + H[7]));
    } else if (b == 132) {
        topk_block(g_entropy2, rows_s, cand, t);
        if (t < PATCH) g_fidx[t] = rows_s[t];
    }

    grid_barrier();

    // ============ Phase D: recon (0..31, one row each) | sims+argsort (32) ===========
    if (b < 32) {
        const int row = g_fidx[b];
        const float inv = 1.0f / 33.0f;
        float4 x = reinterpret_cast<const float4*>(g_agg + (size_t)row * D)[t];
        float4 r;
        r.x = trunc_clip(x.x * inv);
        r.y = trunc_clip(x.y * inv);
        r.z = trunc_clip(x.z * inv);
        r.w = trunc_clip(x.w * inv);
        reinterpret_cast<float4*>(out + (size_t)row * D)[t] = r;
    } else if (b == 32) {
        const float nq = sqrtf((g_norm4[NMEM * 4 + 0] + g_norm4[NMEM * 4 + 1]) +
                               (g_norm4[NMEM * 4 + 2] + g_norm4[NMEM * 4 + 3]));
#pragma unroll
        for (int mi = 0; mi < 4; mi++) {
            const int n = w + 8 * mi;
            const float4* en = reinterpret_cast<const float4*>(g_emb + (size_t)n * D) + l * 8;
            const float4* eq = reinterpret_cast<const float4*>(g_emb + (size_t)NMEM * D) + l * 8;
            float a0 = 0.f, a1 = 0.f, a2 = 0.f, a3 = 0.f;
#pragma unroll
            for (int j = 0; j < 8; j++) {
                float4 x = en[j], y = eq[j];
                a0 = fmaf(x.x, y.x, a0);
                a1 = fmaf(x.y, y.y, a1);
                a2 = fmaf(x.z, y.z, a2);
                a3 = fmaf(x.w, y.w, a3);
            }
            float p = (a0 + a1) + (a2 + a3);
#pragma unroll
            for (int off = 16; off; off >>= 1) p += __shfl_xor_sync(0xffffffffu, p, off);
            if (l == 0) {
                const float nn = sqrtf((g_norm4[n * 4 + 0] + g_norm4[n * 4 + 1]) +
                                       (g_norm4[n * 4 + 2] + g_norm4[n * 4 + 3]));
                const float sim = p / (fmaxf(nn, 1e-8f) * fmaxf(nq, 1e-8f)) * pm[n];
                out[(size_t)S * D + n] = sim;
                ssim[n] = sim;
            }
        }
        __syncthreads();
        if (t < NMEM) {
            const float v = ssim[t];
            int r = 0;
#pragma unroll
            for (int i = 0; i < NMEM; i++) {
                const float vi = ssim[i];
                r += ((vi > v) || (vi == v && i < t)) ? 1 : 0;
            }
            out[(size_t)S * D + NMEM + r] = (float)t;
        }
    }
}

// ---------------- launch ------------------------------------------------------------
extern "C" void kernel_launch(void* const* d_in, const int* in_sizes, int n_in,
                              void* d_out, int out_size)
{
    const float* query    = (const float*)d_in[0];
    const float* memories = (const float*)d_in[1];
    const float* surprise = (const float*)d_in[2];
    const float* pm       = (const float*)d_in[3];
    const float* W1       = (const float*)d_in[4];
    const float* b1       = (const float*)d_in[5];
    const float* W2       = (const float*)d_in[6];
    const float* b2       = (const float*)d_in[7];
    float* out = (float*)d_out;

    bigpass_kernel<<<NMEM * RTILES + 64, 128>>>(memories, query, out);
    tail_kernel<<<TAILB, 256>>>(memories, surprise, pm, W1, b1, W2, b2, out);
}

// round 11
// speedup vs baseline: 3.9904x; 1.1163x over previous
#include <cuda_runtime.h>
#include <cuda_bf16.h>
#include <float.h>
#include <math.h>

#define S 2048
#define D 1024
#define NMEM 32
#define PATCH 32
#define RTILES 64                 // tiles per memory for big rowstats (32 rows each)
#define TAILB 164                 // tail grid
#define CANDMAX 320               // histogram-topk candidate buffer

// ---------------- scratch (static device globals; no allocation) ----------------
__device__ float g_entropy [NMEM * S];
__device__ float g_entropy2[S];
__device__ float g_part    [(NMEM + 1) * RTILES * D];   // slot n*64+p (query n=32)
__device__ float g_colmean [(NMEM + 1) * D];
__device__ float g_agg     [S * D];                     // query + patches (= 33*aggregated)
__device__ float g_h1p     [32 * (NMEM + 1) * 128];     // layer-1 K-split partials
__device__ float g_emb     [(NMEM + 1) * D];
__device__ float g_norm4   [(NMEM + 1) * 4];
__device__ int   g_fidx    [PATCH];
__device__ float g_wsink;
__device__ unsigned g_cnt = 0;
__device__ volatile unsigned g_gen;

// ---------------- cp.async helpers --------------------------------------------------
__device__ __forceinline__ void cp_async16(float* sdst, const float* gsrc)
{
    unsigned sa = (unsigned)__cvta_generic_to_shared(sdst);
    asm volatile("cp.async.cg.shared.global [%0], [%1], 16;" :: "r"(sa), "l"(gsrc) : "memory");
}
__device__ __forceinline__ void issue_chunk(const float* g, float* slot, int l)
{
#pragma unroll
    for (int j = 0; j < 4; j++)
        cp_async16(slot + (l + 32 * j) * 4, g + (l + 32 * j) * 4);
    asm volatile("cp.async.commit_group;" ::: "memory");
}

// =====================================================================================
// K0: fused big pass (at LTS-cap roofline; unchanged).
// =====================================================================================
__global__ void __launch_bounds__(128)
bigpass_kernel(const float* __restrict__ mem, const float* __restrict__ q,
               float* __restrict__ out)
{
    __shared__ float sm[8192];
    const int bx = blockIdx.x;
    const int t = threadIdx.x;
    const int w = t >> 5, l = t & 31;

    if (bx < NMEM * RTILES) {
        const int tile = bx & (RTILES - 1);
        const int n    = bx >> 6;
        const int row0 = tile * 32 + w * 8;
        const float* rowbase = mem + (size_t)n * S * D + (size_t)row0 * D;
        float* ring = sm + w * 2048;

        issue_chunk(rowbase + 0,         ring + 0 * 512, l);
        issue_chunk(rowbase + 512,       ring + 1 * 512, l);
        issue_chunk(rowbase + (size_t)D, ring + 2 * 512, l);

        float4 colacc[8];
#pragma unroll
        for (int j = 0; j < 8; j++) colacc[j] = make_float4(0.f, 0.f, 0.f, 0.f);
        float s1[8], s2[8];
#pragma unroll
        for (int k = 0; k < 8; k++) { s1[k] = 0.f; s2[k] = 0.f; }

#pragma unroll
        for (int k = 0; k < 16; k++) {
            if (k <= 13)      asm volatile("cp.async.wait_group 2;" ::: "memory");
            else if (k == 14) asm volatile("cp.async.wait_group 1;" ::: "memory");
            else              asm volatile("cp.async.wait_group 0;" ::: "memory");
            const float4* rp = reinterpret_cast<const float4*>(ring + (k & 3) * 512);
            const int half = k & 1;
            float a = 0.f, b = 0.f;
#pragma unroll
            for (int j = 0; j < 4; j++) {
                float4 x = rp[l + 32 * j];
                const int c = half * 4 + j;
                colacc[c].x += x.x; colacc[c].y += x.y; colacc[c].z += x.z; colacc[c].w += x.w;
                a += (x.x + x.y) + (x.z + x.w);
                b += (x.x * x.x + x.y * x.y) + (x.z * x.z + x.w * x.w);
            }
            s1[k >> 1] += a; s2[k >> 1] += b;
            if (k < 13) {
                const int kn = k + 3;
                issue_chunk(rowbase + (size_t)(kn >> 1) * D + (kn & 1) * 512,
                            ring + (kn & 3) * 512, l);
            }
        }

#pragma unroll
        for (int off = 16; off; off >>= 1) {
#pragma unroll
            for (int k = 0; k < 8; k++) {
                s1[k] += __shfl_xor_sync(0xffffffffu, s1[k], off);
                s2[k] += __shfl_xor_sync(0xffffffffu, s2[k], off);
            }
        }
#pragma unroll
        for (int k = 0; k < 8; k++) {
            if (l == k) {
                float var = (s2[k] - s1[k] * s1[k] * (1.0f / (float)D)) * (1.0f / (float)(D - 1));
                g_entropy[(size_t)n * S + row0 + k] = var > 0.f ? sqrtf(var) : 0.f;
            }
        }

        __syncthreads();
        float* cs = sm;
#pragma unroll
        for (int h = 0; h < 2; h++)
#pragma unroll
            for (int j = 0; j < 4; j++)
                reinterpret_cast<float4*>(&cs[w * 1024 + h * 512 + 4 * (l + 32 * j)])[0]
                    = colacc[h * 4 + j];
        __syncthreads();
#pragma unroll
        for (int g = 0; g < 8; g++) {
            const int d = t + 128 * g;
            g_part[(size_t)bx * D + d] = ((cs[0 * 1024 + d] + cs[1 * 1024 + d]) +
                                          (cs[2 * 1024 + d] + cs[3 * 1024 + d]));
        }
    } else {
        const int qb = bx - NMEM * RTILES;        // 0..63
        const int row0 = qb * 32;
        float cs[8];
#pragma unroll
        for (int g = 0; g < 8; g++) cs[g] = 0.f;
#pragma unroll 2
        for (int r = 0; r < 32; r++) {
            const size_t base = (size_t)(row0 + r) * D;
#pragma unroll
            for (int g = 0; g < 8; g++) {
                const int d = t + 128 * g;
                float v = q[base + d];
                cs[g] += v;
                g_agg[base + d] = v;
                out[base + d] = 0.f;
            }
        }
        const size_t pb = (size_t)(NMEM * RTILES + qb) * D;
#pragma unroll
        for (int g = 0; g < 8; g++) g_part[pb + t + 128 * g] = cs[g];
    }
}

// =====================================================================================
// K1: mega-tail with software grid barriers.
// =====================================================================================
__device__ __forceinline__ void grid_barrier()
{
    __threadfence();
    __syncthreads();
    if (threadIdx.x == 0) {
        const unsigned gen0 = g_gen;
        __threadfence();
        if (atomicAdd(&g_cnt, 1) == gridDim.x - 1) {
            atomicExch(&g_cnt, 0);
            __threadfence();
            atomicAdd((unsigned*)&g_gen, 1);
        } else {
            while (g_gen == gen0) { __nanosleep(64); }
        }
    }
    __syncthreads();
    __threadfence();
}

struct TopkScratch {
    int bins[1024];
    unsigned long long cb[CANDMAX];   // candidate keys; also reused by fallback (256 u64)
    float rmin[8], rmax[8];
    float vmin, vmax;
    int cnt, thr, total;
};

// exact fallback: 32 serial selection rounds (used only on degenerate data)
__device__ void topk_iter(const float* __restrict__ e, int* rows_s,
                          unsigned long long* cand, int t)
{
    const int w = t >> 5, l = t & 31;
    unsigned long long key[8];
#pragma unroll
    for (int j = 0; j < 8; j++) {
        const int loc = w * 256 + l + 32 * j;
        key[j] = ((unsigned long long)__float_as_uint(e[loc]) << 32) | (unsigned)(~loc);
    }
    for (int it = 0; it < 32; it++) {
        unsigned long long m = key[0];
#pragma unroll
        for (int j = 1; j < 8; j++) m = (key[j] > m) ? key[j] : m;
#pragma unroll
        for (int off = 16; off; off >>= 1) {
            unsigned long long o = __shfl_xor_sync(0xffffffffu, m, off);
            m = (o > m) ? o : m;
        }
        if (l == 0) cand[w * 32 + it] = m;
#pragma unroll
        for (int j = 0; j < 8; j++) if (key[j] == m) key[j] = 0ull;
    }
    __syncthreads();
    const unsigned long long k = cand[t];
    int r = 0;
#pragma unroll 8
    for (int i = 0; i < 256; i++) r += (cand[i] > k) ? 1 : 0;
    if (r < PATCH) rows_s[r] = (int)(~(unsigned)k);
    __syncthreads();
}

// histogram-based exact top-32 of 2048 non-negative floats (256 threads)
__device__ void topk_hist(const float* __restrict__ e, int* rows_s,
                          TopkScratch* sc, int t)
{
    const int w = t >> 5, l = t & 31;
    float v[8];
    float mn = FLT_MAX, mx = -FLT_MAX;
#pragma unroll
    for (int j = 0; j < 8; j++) {
        v[j] = e[t + 256 * j];
        mn = fminf(mn, v[j]);
        mx = fmaxf(mx, v[j]);
    }
#pragma unroll
    for (int off = 16; off; off >>= 1) {
        mn = fminf(mn, __shfl_xor_sync(0xffffffffu, mn, off));
        mx = fmaxf(mx, __shfl_xor_sync(0xffffffffu, mx, off));
    }
    if (l == 0) { sc->rmin[w] = mn; sc->rmax[w] = mx; }
    // zero bins + cnt while min/max settles
#pragma unroll
    for (int j = 0; j < 4; j++) sc->bins[t + 256 * j] = 0;
    if (t == 0) sc->cnt = 0;
    __syncthreads();
    if (t == 0) {
        float a = sc->rmin[0], b = sc->rmax[0];
#pragma unroll
        for (int j = 1; j < 8; j++) { a = fminf(a, sc->rmin[j]); b = fmaxf(b, sc->rmax[j]); }
        sc->vmin = a; sc->vmax = b;
    }
    __syncthreads();
    const float vmin = sc->vmin;
    const float scale = 1023.0f / fmaxf(sc->vmax - vmin, 1e-30f);
    int bn[8];
#pragma unroll
    for (int j = 0; j < 8; j++) {
        int b = (int)((v[j] - vmin) * scale);
        bn[j] = b < 0 ? 0 : (b > 1023 ? 1023 : b);
        atomicAdd(&sc->bins[bn[j]], 1);
    }
    __syncthreads();
    // warp 0: suffix counts over 32 groups of 32 bins -> exact threshold bin
    if (w == 0) {
        int gs = 0;
#pragma unroll
        for (int k = 0; k < 32; k++) gs += sc->bins[l * 32 + k];
        int suf = gs;
#pragma unroll
        for (int off = 1; off < 32; off <<= 1) {
            int o = __shfl_down_sync(0xffffffffu, suf, off);
            if (l + off < 32) suf += o;
        }
        int sufn = __shfl_down_sync(0xffffffffu, suf, 1);
        if (l == 31) sufn = 0;
        if (suf >= PATCH && sufn < PATCH) {         // unique lane
            int c = sufn, bb = 0;
            for (int k = 31; k >= 0; k--) {
                c += sc->bins[l * 32 + k];
                if (c >= PATCH) { bb = l * 32 + k; break; }
            }
            sc->thr = bb; sc->total = c;
        }
    }
    __syncthreads();
    const int thr = sc->thr, total = sc->total;
    if (total <= CANDMAX) {
#pragma unroll
        for (int j = 0; j < 8; j++) {
            if (bn[j] >= thr) {
                int p = atomicAdd(&sc->cnt, 1);
                sc->cb[p] = ((unsigned long long)__float_as_uint(v[j]) << 32)
                            | (unsigned)(~(t + 256 * j));
            }
        }
        __syncthreads();
        if (t < total) {
            const unsigned long long k = sc->cb[t];
            int r = 0;
            for (int i = 0; i < total; i++) r += (sc->cb[i] > k) ? 1 : 0;
            if (r < PATCH) rows_s[r] = (int)(~(unsigned)k);
        }
        __syncthreads();
    } else {
        topk_iter(e, rows_s, sc->cb, t);            // degenerate data fallback (exact)
    }
}

__device__ __forceinline__ float trunc_clip(float x)
{
    return truncf(fminf(fmaxf(x, -128.f), 127.f));
}

__global__ void __launch_bounds__(256)
tail_kernel(const float* __restrict__ mem, const float* __restrict__ surprise,
            const float* __restrict__ pm,
            const float* __restrict__ W1, const float* __restrict__ b1,
            const float* __restrict__ W2, const float* __restrict__ b2,
            float* __restrict__ out)
{
    __shared__ TopkScratch sc;
    __shared__ int rows_s[PATCH];
    __shared__ float sf[(NMEM + 1) * 32];
    __shared__ float H[128];
    __shared__ float ssim[NMEM];

    const int b = blockIdx.x, t = threadIdx.x;
    const int w = t >> 5, l = t & 31;

    // ===== Phase A: topk+scatter (0..31) | colmean (32..97) | warm W1/W2 (98..163) ===
    if (b < 32) {
        const int n = b;
        topk_hist(g_entropy + (size_t)n * S, rows_s, &sc, t);
        const float* mb = mem + (size_t)n * S * D;
#pragma unroll
        for (int jb = 0; jb < 32; jb += 8) {
            float4 x[8];
#pragma unroll
            for (int j = 0; j < 8; j++)
                x[j] = reinterpret_cast<const float4*>(mb + (size_t)rows_s[jb + j] * D)[t];
#pragma unroll
            for (int j = 0; j < 8; j++) {
                float* dst = g_agg + (size_t)rows_s[jb + j] * D + 4 * t;
                atomicAdd(dst + 0, trunc_clip(x[j].x));
                atomicAdd(dst + 1, trunc_clip(x[j].y));
                atomicAdd(dst + 2, trunc_clip(x[j].z));
                atomicAdd(dst + 3, trunc_clip(x[j].w));
            }
        }
    } else if (b < 98) {
        const int m = b - 32;                // 0..65: source n, half hf
        const int n = m >> 1, hf = m & 1;
#pragma unroll
        for (int g = 0; g < 2; g++) {
            const int d = hf * 512 + g * 256 + t;
            const size_t base = (size_t)(n * RTILES) * D + d;
            float s = 0.f;
#pragma unroll 16
            for (int p = 0; p < RTILES; p++) s += g_part[base + (size_t)p * D];
            g_colmean[(size_t)n * D + d] = s * (1.0f / (float)S);
        }
    } else {
        const int j = b - 98;                // 0..65: warm W1+W2 into L2
        float acc = 0.f;
        for (int i = j * 256 + t; i < 1027 * 128; i += 66 * 256) acc += W1[i];
        for (int i = j * 256 + t; i < 128 * D;    i += 66 * 256) acc += W2[i];
        if (acc == 1.2345678e30f) g_wsink = acc;   // never true; defeats DCE
    }

    grid_barrier();

    // ===== Phase B: entropy_agg (0..127) | mlp1 (128..159) ===========================
    if (b < 128) {
#pragma unroll
        for (int r = 0; r < 2; r++) {
            const int row = b * 16 + w * 2 + r;
            const float4* rp = reinterpret_cast<const float4*>(g_agg + (size_t)row * D);
            float a = 0.f, bb = 0.f;
#pragma unroll
            for (int j = 0; j < 8; j++) {
                float4 x = rp[l + 32 * j];
                a += (x.x + x.y) + (x.z + x.w);
                bb += (x.x * x.x + x.y * x.y) + (x.z * x.z + x.w * x.w);
            }
#pragma unroll
            for (int off = 16; off; off >>= 1) {
                a += __shfl_xor_sync(0xffffffffu, a, off);
                bb += __shfl_xor_sync(0xffffffffu, bb, off);
            }
            if (l == 0) {
                float var = (bb - a * a * (1.0f / (float)D)) * (1.0f / (float)(D - 1));
                g_entropy2[row] = var > 0.f ? sqrtf(var) : 0.f;
            }
        }
    } else if (b < 160) {
        const int c = b - 128;               // mlp1 K-chunk: W1 rows [c*32, c*32+32)
        for (int idx = t; idx < (NMEM + 1) * 32; idx += 256) {
            const int n = idx >> 5, kk = idx & 31;
            sf[idx] = g_colmean[(size_t)n * D + c * 32 + kk];
        }
        __syncthreads();
        if (t < 128) {
            float acc[NMEM + 1];
#pragma unroll
            for (int n = 0; n <= NMEM; n++) acc[n] = 0.f;
#pragma unroll 4
            for (int kk = 0; kk < 32; kk++) {
                const float wv = W1[(size_t)(c * 32 + kk) * 128 + t];
#pragma unroll
                for (int n = 0; n <= NMEM; n++) acc[n] = fmaf(sf[n * 32 + kk], wv, acc[n]);
            }
#pragma unroll
            for (int n = 0; n <= NMEM; n++)
                g_h1p[(size_t)(c * (NMEM + 1) + n) * 128 + t] = acc[n];
        }
    }

    grid_barrier();

    // ===== Phase C: mlp2 (0..131) | final topk (132) =================================
    if (b < 132) {
        const int n = b >> 2, c = b & 3;
        if (t < 128) {
            float h = b1[t];
#pragma unroll 8
            for (int cc = 0; cc < 32; cc++)
                h += g_h1p[(size_t)(cc * (NMEM + 1) + n) * 128 + t];
            if (n < NMEM) h = fmaf(surprise[n], W1[(size_t)1024 * 128 + t], h);
            H[t] = h > 0.f ? h : 0.f;
        }
        __syncthreads();
        const int d = c * 256 + t;
        float e0 = b2[d], e1 = 0.f, e2 = 0.f, e3 = 0.f;
        float e4 = 0.f, e5 = 0.f, e6 = 0.f, e7 = 0.f;
#pragma unroll 4
        for (int k = 0; k < 128; k += 8) {
            e0 = fmaf(H[k + 0], W2[(size_t)(k + 0) * D + d], e0);
            e1 = fmaf(H[k + 1], W2[(size_t)(k + 1) * D + d], e1);
            e2 = fmaf(H[k + 2], W2[(size_t)(k + 2) * D + d], e2);
            e3 = fmaf(H[k + 3], W2[(size_t)(k + 3) * D + d], e3);
            e4 = fmaf(H[k + 4], W2[(size_t)(k + 4) * D + d], e4);
            e5 = fmaf(H[k + 5], W2[(size_t)(k + 5) * D + d], e5);
            e6 = fmaf(H[k + 6], W2[(size_t)(k + 6) * D + d], e6);
            e7 = fmaf(H[k + 7], W2[(size_t)(k + 7) * D + d], e7);
        }
        const float e = ((e0 + e1) + (e2 + e3)) + ((e4 + e5) + (e6 + e7));
        g_emb[(size_t)n * D + d] = e;
        float nrm = e * e;
#pragma unroll
        for (int off = 16; off; off >>= 1) nrm += __shfl_xor_sync(0xffffffffu, nrm, off);
        __syncthreads();                    // reuse H as reduction scratch
        if (l == 0) H[w] = nrm;
        __syncthreads();
        if (t == 0)
            g_norm4[n * 4 + c] = ((H[0] + H[1]) + (H[2] + H[3])) +
                                 ((H[4] + H[5]) + (H[6] + H[7]));
    } else if (b == 132) {
        topk_hist(g_entropy2, rows_s, &sc, t);
        if (t < PATCH) g_fidx[t] = rows_s[t];
    }

    grid_barrier();

    // ===== Phase D: recon (0..31, one row each) | sims+argsort (32) ==================
    if (b < 32) {
        const int row = g_fidx[b];
        const float inv = 1.0f / 33.0f;
        float4 x = reinterpret_cast<const float4*>(g_agg + (size_t)row * D)[t];
        float4 r;
        r.x = trunc_clip(x.x * inv);
        r.y = trunc_clip(x.y * inv);
        r.z = trunc_clip(x.z * inv);
        r.w = trunc_clip(x.w * inv);
        reinterpret_cast<float4*>(out + (size_t)row * D)[t] = r;
    } else if (b == 32) {
        const float nq = sqrtf((g_norm4[NMEM * 4 + 0] + g_norm4[NMEM * 4 + 1]) +
                               (g_norm4[NMEM * 4 + 2] + g_norm4[NMEM * 4 + 3]));
#pragma unroll
        for (int mi = 0; mi < 4; mi++) {
            const int n = w + 8 * mi;
            const float4* en = reinterpret_cast<const float4*>(g_emb + (size_t)n * D) + l * 8;
            const float4* eq = reinterpret_cast<const float4*>(g_emb + (size_t)NMEM * D) + l * 8;
            float a0 = 0.f, a1 = 0.f, a2 = 0.f, a3 = 0.f;
#pragma unroll
            for (int j = 0; j < 8; j++) {
                float4 x = en[j], y = eq[j];
                a0 = fmaf(x.x, y.x, a0);
                a1 = fmaf(x.y, y.y, a1);
                a2 = fmaf(x.z, y.z, a2);
                a3 = fmaf(x.w, y.w, a3);
            }
            float p = (a0 + a1) + (a2 + a3);
#pragma unroll
            for (int off = 16; off; off >>= 1) p += __shfl_xor_sync(0xffffffffu, p, off);
            if (l == 0) {
                const float nn = sqrtf((g_norm4[n * 4 + 0] + g_norm4[n * 4 + 1]) +
                                       (g_norm4[n * 4 + 2] + g_norm4[n * 4 + 3]));
                const float sim = p / (fmaxf(nn, 1e-8f) * fmaxf(nq, 1e-8f)) * pm[n];
                out[(size_t)S * D + n] = sim;
                ssim[n] = sim;
            }
        }
        __syncthreads();
        if (t < NMEM) {
            const float v = ssim[t];
            int r = 0;
#pragma unroll
            for (int i = 0; i < NMEM; i++) {
                const float vi = ssim[i];
                r += ((vi > v) || (vi == v && i < t)) ? 1 : 0;
            }
            out[(size_t)S * D + NMEM + r] = (float)t;
        }
    }
}

// ---------------- launch ------------------------------------------------------------
extern "C" void kernel_launch(void* const* d_in, const int* in_sizes, int n_in,
                              void* d_out, int out_size)
{
    const float* query    = (const float*)d_in[0];
    const float* memories = (const float*)d_in[1];
    const float* surprise = (const float*)d_in[2];
    const float* pm       = (const float*)d_in[3];
    const float* W1       = (const float*)d_in[4];
    const float* b1       = (const float*)d_in[5];
    const float* W2       = (const float*)d_in[6];
    const float* b2       = (const float*)d_in[7];
    float* out = (float*)d_out;

    bigpass_kernel<<<NMEM * RTILES + 64, 128>>>(memories, query, out);
    tail_kernel<<<TAILB, 256>>>(memories, surprise, pm, W1, b1, W2, b2, out);
}